// round 10
// baseline (speedup 1.0000x reference)
#include <cuda_runtime.h>
#include <cuda_bf16.h>
#include <float.h>
#include <stdint.h>

#define N_Q   4096
#define M_P   32768
#define W_F   768
#define K_NN  4
#define R2    0.25f
#define K_TOT (K_NN * W_F)        // 3072
#define IDX_SENT 0x7FFFFFFF
#define QB    8                    // queries per block (amortize point traffic)

// ---------------- scratch (static device memory; no allocs allowed) --------
__device__ int            g_idx[N_Q * K_NN];
__device__ float          g_aggraw[N_Q * W_F];
__device__ float4         g_pts4[M_P];
__device__ __nv_bfloat16  g_Ah[(size_t)N_Q * K_TOT];   // gathered A, hi plane
__device__ __nv_bfloat16  g_Al[(size_t)N_Q * K_TOT];   // gathered A, lo plane
__device__ __nv_bfloat16  g_Bh[(size_t)K_TOT * W_F];   // Wagg hi plane [3072][768]
__device__ __nv_bfloat16  g_Bl[(size_t)K_TOT * W_F];   // Wagg lo plane

__device__ __forceinline__ bool pair_less(float d1, int i1, float d2, int i2) {
    return (d1 < d2) || (d1 == d2 && i1 < i2);
}

__device__ __forceinline__ uint32_t smem_u32(const void* p) {
    uint32_t a;
    asm("{ .reg .u64 t; cvta.to.shared.u64 t, %1; cvt.u32.u64 %0, t; }"
        : "=r"(a) : "l"(p));
    return a;
}

// ---------------------------------------------------------------------------
// Kernel 0: pack pts -> {x,y,z,pp}; pp in exact reference association
// (descending FMA — validated R5, FROZEN).
// ---------------------------------------------------------------------------
__global__ __launch_bounds__(256) void pack_kernel(const float* __restrict__ pts) {
    const int j = blockIdx.x * 256 + threadIdx.x;
    if (j < M_P) {
        const float px = pts[j * 3 + 0];
        const float py = pts[j * 3 + 1];
        const float pz = pts[j * 3 + 2];
        const float pp = __fmaf_rn(px, px, __fmaf_rn(py, py, __fmul_rn(pz, pz)));
        g_pts4[j] = make_float4(px, py, pz, pp);
    }
}

// ---------------------------------------------------------------------------
// Kernel 1: top-4 NN, QB queries per block. Arithmetic FROZEN (R5 bit-exact).
// Radius-pruned sentinel lists; rare-branch insert (validated R9).
// Each point float4 is loaded ONCE and tested against QB queries -> L2
// traffic / QB.
// ---------------------------------------------------------------------------
__device__ __forceinline__ void try_insert(float d2, int j, float* bd, int* bi) {
    if (d2 <= bd[3]) {                          // rare (~0.05%)
        if (pair_less(d2, j, bd[3], bi[3])) {
            bd[3] = d2; bi[3] = j;
            #pragma unroll
            for (int q = 3; q > 0; --q) {
                if (pair_less(bd[q], bi[q], bd[q - 1], bi[q - 1])) {
                    float td = bd[q]; bd[q] = bd[q - 1]; bd[q - 1] = td;
                    int   ti = bi[q]; bi[q] = bi[q - 1]; bi[q - 1] = ti;
                }
            }
        }
    }
}

__global__ __launch_bounds__(256) void topk_kernel(const float* __restrict__ q_pos) {
    const int q0  = blockIdx.x * QB;
    const int tid = threadIdx.x;

    float qx[QB], qy[QB], qz[QB], qq[QB];
    #pragma unroll
    for (int q = 0; q < QB; q++) {
        qx[q] = q_pos[(q0 + q) * 3 + 0];
        qy[q] = q_pos[(q0 + q) * 3 + 1];
        qz[q] = q_pos[(q0 + q) * 3 + 2];
        qq[q] = __fmaf_rn(qx[q], qx[q],
                 __fmaf_rn(qy[q], qy[q], __fmul_rn(qz[q], qz[q])));
    }

    float bd[QB][4];
    int   bi[QB][4];
    #pragma unroll
    for (int q = 0; q < QB; q++)
        #pragma unroll
        for (int k = 0; k < 4; k++) { bd[q][k] = R2; bi[q][k] = IDX_SENT; }

    // 128 points per thread, 2-way unroll for load latency.
    #pragma unroll 1
    for (int it = 0; it < M_P / (256 * 2); it++) {
        const int jb = it * 512 + tid;
        const float4 p0 = g_pts4[jb];
        const float4 p1 = g_pts4[jb + 256];

        #pragma unroll
        for (int q = 0; q < QB; q++) {
            float dot = __fmul_rn(qx[q], p0.x);
            dot = __fmaf_rn(qy[q], p0.y, dot);
            dot = __fmaf_rn(qz[q], p0.z, dot);
            const float t1 = __fadd_rn(qq[q], p0.w);
            const float d2 = __fadd_rn(t1, -__fmul_rn(2.0f, dot));
            try_insert(d2, jb, bd[q], bi[q]);
        }
        #pragma unroll
        for (int q = 0; q < QB; q++) {
            float dot = __fmul_rn(qx[q], p1.x);
            dot = __fmaf_rn(qy[q], p1.y, dot);
            dot = __fmaf_rn(qz[q], p1.z, dot);
            const float t1 = __fadd_rn(qq[q], p1.w);
            const float d2 = __fadd_rn(t1, -__fmul_rn(2.0f, dot));
            try_insert(d2, jb + 256, bd[q], bi[q]);
        }
    }

    __shared__ float sd[256 * 4];
    __shared__ int   si[256 * 4];

    #pragma unroll 1
    for (int q = 0; q < QB; q++) {
        __syncthreads();
        #pragma unroll
        for (int k = 0; k < 4; k++) {
            sd[tid * 4 + k] = bd[q][k];
            si[tid * 4 + k] = bi[q][k];
        }
        __syncthreads();

        for (int s = 128; s > 0; s >>= 1) {
            if (tid < s) {
                float ad[4], xd[4]; int ai[4], xi[4];
                #pragma unroll
                for (int k = 0; k < 4; k++) {
                    ad[k] = sd[tid * 4 + k];        ai[k] = si[tid * 4 + k];
                    xd[k] = sd[(tid + s) * 4 + k];  xi[k] = si[(tid + s) * 4 + k];
                }
                float rd[4]; int ri[4];
                int ia = 0, ib = 0;
                #pragma unroll
                for (int t = 0; t < 4; t++) {
                    bool takeA = pair_less(ad[ia], ai[ia], xd[ib], xi[ib]);
                    rd[t] = takeA ? ad[ia] : xd[ib];
                    ri[t] = takeA ? ai[ia] : xi[ib];
                    if (takeA) ia++; else ib++;
                }
                #pragma unroll
                for (int k = 0; k < 4; k++) { sd[tid * 4 + k] = rd[k]; si[tid * 4 + k] = ri[k]; }
            }
            __syncthreads();
        }

        if (tid == 0) {
            #pragma unroll
            for (int k = 0; k < 4; k++)
                g_idx[(q0 + q) * 4 + k] = (si[k] == IDX_SENT) ? -1 : si[k];
        }
    }
}

// ---------------------------------------------------------------------------
// bf16 split: x = hi + lo (+ ~2^-17 residual)
// ---------------------------------------------------------------------------
__device__ __forceinline__ void bf16_split(float x, __nv_bfloat16& hi, __nv_bfloat16& lo) {
    hi = __float2bfloat16_rn(x);
    lo = __float2bfloat16_rn(x - __bfloat162float(hi));
}

// ---------------------------------------------------------------------------
// Kernel 2a: elementwise split Wagg[3072][768] -> g_Bh/g_Bl (same layout)
// ---------------------------------------------------------------------------
__global__ __launch_bounds__(256) void wsplit_kernel(const float* __restrict__ Wagg) {
    const size_t id = (size_t)blockIdx.x * 256 + threadIdx.x;   // float4 index
    const float4 v = reinterpret_cast<const float4*>(Wagg)[id];
    __nv_bfloat16 h0,h1,h2,h3,l0,l1,l2,l3;
    bf16_split(v.x, h0, l0);
    bf16_split(v.y, h1, l1);
    bf16_split(v.z, h2, l2);
    bf16_split(v.w, h3, l3);
    __nv_bfloat162* ph = reinterpret_cast<__nv_bfloat162*>(g_Bh) + id * 2;
    __nv_bfloat162* pl = reinterpret_cast<__nv_bfloat162*>(g_Bl) + id * 2;
    ph[0] = __nv_bfloat162(h0, h1);
    ph[1] = __nv_bfloat162(h2, h3);
    pl[0] = __nv_bfloat162(l0, l1);
    pl[1] = __nv_bfloat162(l2, l3);
}

// ---------------------------------------------------------------------------
// Kernel 2b: gather + split feats -> g_Ah/g_Al [4096][3072]
// ---------------------------------------------------------------------------
__global__ __launch_bounds__(256) void gather_kernel(const float* __restrict__ feats) {
    const int n = blockIdx.x;
    __shared__ int sl[4];
    if (threadIdx.x < 4) sl[threadIdx.x] = g_idx[n * 4 + threadIdx.x];
    __syncthreads();

    #pragma unroll
    for (int k = 0; k < 4; k++) {
        const int prow = sl[k];
        const int t = threadIdx.x;
        if (t < 192) {
            float4 v = make_float4(0.f, 0.f, 0.f, 0.f);
            if (prow >= 0)
                v = *reinterpret_cast<const float4*>(&feats[(size_t)prow * W_F + t * 4]);
            __nv_bfloat16 h0,h1,h2,h3,l0,l1,l2,l3;
            bf16_split(v.x, h0, l0);
            bf16_split(v.y, h1, l1);
            bf16_split(v.z, h2, l2);
            bf16_split(v.w, h3, l3);
            const size_t off = (size_t)n * K_TOT + k * W_F + t * 4;
            __nv_bfloat162* ph = reinterpret_cast<__nv_bfloat162*>(&g_Ah[off]);
            __nv_bfloat162* pl = reinterpret_cast<__nv_bfloat162*>(&g_Al[off]);
            ph[0] = __nv_bfloat162(h0, h1);
            ph[1] = __nv_bfloat162(h2, h3);
            pl[0] = __nv_bfloat162(l0, l1);
            pl[1] = __nv_bfloat162(l2, l3);
        }
    }
}

// ---------------------------------------------------------------------------
// Kernel 3: bf16 mma.sync GEMM — C = A·W, 3 plane products, fp32 accum.
// CTA 128x64, K-tile 32, 8 warps (4m x 2n), 3-stage cp.async. (unchanged;
// at legacy-HMMA roofline)
// ---------------------------------------------------------------------------
#define CTA_M 128
#define CTA_N 64
#define CTA_K 32
#define STAGES 3
#define NKIT (K_TOT / CTA_K)            // 96
#define LDA_B 80
#define LDB_B 144
#define A_PLANE_B (CTA_M * LDA_B)
#define B_PLANE_B (CTA_K * LDB_B)
#define STAGE_B (2 * A_PLANE_B + 2 * B_PLANE_B)
#define GEMM_SMEM (STAGES * STAGE_B)

#define CP_ASYNC16(saddr, gaddr) \
    asm volatile("cp.async.cg.shared.global [%0], [%1], 16;" :: "r"(saddr), "l"(gaddr))
#define CP_COMMIT()  asm volatile("cp.async.commit_group;" ::: "memory")
#define CP_WAIT(n)   asm volatile("cp.async.wait_group %0;" :: "n"(n) : "memory")

__device__ __forceinline__ void ldsm_x4(uint32_t& r0, uint32_t& r1, uint32_t& r2,
                                        uint32_t& r3, uint32_t addr) {
    asm volatile("ldmatrix.sync.aligned.m8n8.x4.shared.b16 {%0,%1,%2,%3}, [%4];"
                 : "=r"(r0), "=r"(r1), "=r"(r2), "=r"(r3) : "r"(addr));
}
__device__ __forceinline__ void ldsm_x4_t(uint32_t& r0, uint32_t& r1, uint32_t& r2,
                                          uint32_t& r3, uint32_t addr) {
    asm volatile("ldmatrix.sync.aligned.m8n8.x4.trans.shared.b16 {%0,%1,%2,%3}, [%4];"
                 : "=r"(r0), "=r"(r1), "=r"(r2), "=r"(r3) : "r"(addr));
}
__device__ __forceinline__ void mma16816(float* c, const uint32_t* a, const uint32_t* b) {
    asm volatile(
        "mma.sync.aligned.m16n8k16.row.col.f32.bf16.bf16.f32 "
        "{%0,%1,%2,%3}, {%4,%5,%6,%7}, {%8,%9}, {%0,%1,%2,%3};"
        : "+f"(c[0]), "+f"(c[1]), "+f"(c[2]), "+f"(c[3])
        : "r"(a[0]), "r"(a[1]), "r"(a[2]), "r"(a[3]), "r"(b[0]), "r"(b[1]));
}

__device__ __forceinline__ void load_stage(char* smem, int slot, int kt,
                                           int bm, int bn, int tid) {
    const uint32_t sbase = smem_u32(smem) + (uint32_t)slot * STAGE_B;
    const char* gAh = reinterpret_cast<const char*>(g_Ah);
    const char* gAl = reinterpret_cast<const char*>(g_Al);
    const char* gBh = reinterpret_cast<const char*>(g_Bh);
    const char* gBl = reinterpret_cast<const char*>(g_Bl);

    #pragma unroll
    for (int i = 0; i < 2; i++) {
        const int id  = tid + i * 256;
        const int row = id >> 2;
        const int col = (id & 3) * 16;
        const size_t goff = ((size_t)(bm + row) * K_TOT + kt) * 2 + col;
        CP_ASYNC16(sbase + 0 * A_PLANE_B + row * LDA_B + col, gAh + goff);
        CP_ASYNC16(sbase + 1 * A_PLANE_B + row * LDA_B + col, gAl + goff);
    }
    {
        const int row = tid >> 3;
        const int col = (tid & 7) * 16;
        const size_t goff = ((size_t)(kt + row) * W_F + bn) * 2 + col;
        CP_ASYNC16(sbase + 2 * A_PLANE_B + 0 * B_PLANE_B + row * LDB_B + col, gBh + goff);
        CP_ASYNC16(sbase + 2 * A_PLANE_B + 1 * B_PLANE_B + row * LDB_B + col, gBl + goff);
    }
}

__global__ __launch_bounds__(256) void gemm_mma_kernel(const float* __restrict__ bagg) {
    extern __shared__ char smem[];
    const int tid  = threadIdx.x;
    const int wid  = tid >> 5;
    const int lane = tid & 31;
    const int bm = blockIdx.y * CTA_M;
    const int bn = blockIdx.x * CTA_N;
    const int wm = (wid & 3) * 32;
    const int wn = (wid >> 2) * 32;

    float c[2][4][4];
    #pragma unroll
    for (int mi = 0; mi < 2; mi++)
        #pragma unroll
        for (int ni = 0; ni < 4; ni++)
            #pragma unroll
            for (int r = 0; r < 4; r++) c[mi][ni][r] = 0.0f;

    load_stage(smem, 0, 0, bm, bn, tid); CP_COMMIT();
    load_stage(smem, 1, CTA_K, bm, bn, tid); CP_COMMIT();

    const uint32_t sb = smem_u32(smem);
    const int a_row = wm + (lane & 15);
    const int a_col = (lane >> 4) * 16;
    const int b_row = (lane & 7) + ((lane >> 3) & 1) * 8;
    const int b_col = wn + (lane >> 4) * 8;

    #pragma unroll 1
    for (int it = 0; it < NKIT; it++) {
        CP_WAIT(1);
        __syncthreads();

        if (it + STAGES - 1 < NKIT)
            load_stage(smem, (it + STAGES - 1) % STAGES, (it + STAGES - 1) * CTA_K,
                       bm, bn, tid);
        CP_COMMIT();

        const uint32_t st = sb + (uint32_t)(it % STAGES) * STAGE_B;
        const uint32_t sAh = st;
        const uint32_t sAl = st + A_PLANE_B;
        const uint32_t sBh = st + 2 * A_PLANE_B;
        const uint32_t sBl = sBh + B_PLANE_B;

        #pragma unroll
        for (int k16 = 0; k16 < 2; k16++) {
            uint32_t ah[2][4], al[2][4];
            #pragma unroll
            for (int mi = 0; mi < 2; mi++) {
                const uint32_t off = (uint32_t)((a_row + mi * 16) * LDA_B
                                                + k16 * 32 + a_col);
                ldsm_x4(ah[mi][0], ah[mi][1], ah[mi][2], ah[mi][3], sAh + off);
                ldsm_x4(al[mi][0], al[mi][1], al[mi][2], al[mi][3], sAl + off);
            }
            uint32_t bh[4][2], bl[4][2];
            #pragma unroll
            for (int nh = 0; nh < 2; nh++) {
                const uint32_t off = (uint32_t)((k16 * 16 + b_row) * LDB_B
                                                + (b_col + nh * 16) * 2);
                uint32_t r0, r1, r2, r3;
                ldsm_x4_t(r0, r1, r2, r3, sBh + off);
                bh[nh * 2 + 0][0] = r0; bh[nh * 2 + 0][1] = r1;
                bh[nh * 2 + 1][0] = r2; bh[nh * 2 + 1][1] = r3;
                ldsm_x4_t(r0, r1, r2, r3, sBl + off);
                bl[nh * 2 + 0][0] = r0; bl[nh * 2 + 0][1] = r1;
                bl[nh * 2 + 1][0] = r2; bl[nh * 2 + 1][1] = r3;
            }
            #pragma unroll
            for (int mi = 0; mi < 2; mi++)
                #pragma unroll
                for (int ni = 0; ni < 4; ni++) {
                    mma16816(c[mi][ni], ah[mi], bh[ni]);
                    mma16816(c[mi][ni], ah[mi], bl[ni]);
                    mma16816(c[mi][ni], al[mi], bh[ni]);
                }
        }
        __syncthreads();
    }

    #pragma unroll
    for (int mi = 0; mi < 2; mi++) {
        #pragma unroll
        for (int ni = 0; ni < 4; ni++) {
            const int row0 = bm + wm + mi * 16 + (lane >> 2);
            const int col  = bn + wn + ni * 8 + (lane & 3) * 2;
            const float bx = bagg[col], by = bagg[col + 1];
            float2 o0 = make_float2(c[mi][ni][0] + bx, c[mi][ni][1] + by);
            float2 o1 = make_float2(c[mi][ni][2] + bx, c[mi][ni][3] + by);
            *reinterpret_cast<float2*>(&g_aggraw[(size_t)row0 * W_F + col]) = o0;
            *reinterpret_cast<float2*>(&g_aggraw[(size_t)(row0 + 8) * W_F + col]) = o1;
        }
    }
}

// ---------------------------------------------------------------------------
// Kernel 4: pos embedding GEMV (K=6) + two LayerNorms + add.
// ---------------------------------------------------------------------------
__device__ __forceinline__ float block_sum(float v, float* sbuf) {
    __syncthreads();
    #pragma unroll
    for (int o = 16; o > 0; o >>= 1) v += __shfl_xor_sync(0xffffffffu, v, o);
    const int wid = threadIdx.x >> 5, lane = threadIdx.x & 31;
    if (lane == 0) sbuf[wid] = v;
    __syncthreads();
    if (wid == 0) {
        float x = (lane < 8) ? sbuf[lane] : 0.0f;
        #pragma unroll
        for (int o = 4; o > 0; o >>= 1) x += __shfl_xor_sync(0xffffffffu, x, o);
        if (lane == 0) sbuf[0] = x;
    }
    __syncthreads();
    return sbuf[0];
}

__global__ __launch_bounds__(256) void ln_kernel(const float* __restrict__ pos_in,
                                                 const float* __restrict__ Wpos,
                                                 const float* __restrict__ bpos,
                                                 const float* __restrict__ gagg,
                                                 const float* __restrict__ beagg,
                                                 const float* __restrict__ gpos,
                                                 const float* __restrict__ bepos,
                                                 float* __restrict__ out) {
    const int n   = blockIdx.x;
    const int tid = threadIdx.x;
    __shared__ float pin[6];
    __shared__ float sred[32];
    if (tid < 6) pin[tid] = pos_in[n * 6 + tid];
    __syncthreads();

    float a[3], p[3];
    float sa = 0.f, sp = 0.f;
    #pragma unroll
    for (int t = 0; t < 3; t++) {
        const int j = tid + t * 256;
        a[t] = g_aggraw[n * W_F + j];
        float pv = bpos[j];
        #pragma unroll
        for (int i = 0; i < 6; i++) pv += pin[i] * Wpos[i * W_F + j];
        p[t] = pv;
        sa += a[t]; sp += p[t];
    }
    const float ma = block_sum(sa, sred) * (1.0f / 768.0f);
    const float mp = block_sum(sp, sred) * (1.0f / 768.0f);

    float va = 0.f, vp = 0.f;
    #pragma unroll
    for (int t = 0; t < 3; t++) {
        const float da = a[t] - ma; va += da * da;
        const float dp = p[t] - mp; vp += dp * dp;
    }
    va = block_sum(va, sred) * (1.0f / 768.0f);
    vp = block_sum(vp, sred) * (1.0f / 768.0f);
    const float inva = rsqrtf(va + 1e-12f);
    const float invp = rsqrtf(vp + 1e-12f);

    #pragma unroll
    for (int t = 0; t < 3; t++) {
        const int j = tid + t * 256;
        out[n * W_F + j] = (a[t] - ma) * inva * gagg[j] + beagg[j]
                         + (p[t] - mp) * invp * gpos[j] + bepos[j];
    }
}

// ---------------------------------------------------------------------------
extern "C" void kernel_launch(void* const* d_in, const int* in_sizes, int n_in,
                              void* d_out, int out_size) {
    const float* q_pos  = (const float*)d_in[0];
    const float* pts    = (const float*)d_in[1];
    const float* feats  = (const float*)d_in[2];
    const float* pos_in = (const float*)d_in[3];
    const float* Wagg   = (const float*)d_in[4];
    const float* bagg   = (const float*)d_in[5];
    const float* gagg   = (const float*)d_in[6];
    const float* beagg  = (const float*)d_in[7];
    const float* Wpos   = (const float*)d_in[8];
    const float* bpos   = (const float*)d_in[9];
    const float* gpos   = (const float*)d_in[10];
    const float* bepos  = (const float*)d_in[11];
    float* out = (float*)d_out;

    static int smem_set = 0;
    if (!smem_set) {
        cudaFuncSetAttribute(gemm_mma_kernel,
                             cudaFuncAttributeMaxDynamicSharedMemorySize, GEMM_SMEM);
        smem_set = 1;
    }

    pack_kernel<<<(M_P + 255) / 256, 256>>>(pts);
    topk_kernel<<<N_Q / QB, 256>>>(q_pos);

    wsplit_kernel<<<(K_TOT * W_F / 4) / 256, 256>>>(Wagg);
    gather_kernel<<<N_Q, 256>>>(feats);

    dim3 ggrid(W_F / CTA_N, N_Q / CTA_M);            // 12 x 32 = 384 CTAs
    gemm_mma_kernel<<<ggrid, 256, GEMM_SMEM>>>(bagg);

    ln_kernel<<<N_Q, 256>>>(pos_in, Wpos, bpos, gagg, beagg, gpos, bepos, out);
}

// round 11
// speedup vs baseline: 1.7598x; 1.7598x over previous
#include <cuda_runtime.h>
#include <cuda_bf16.h>
#include <float.h>
#include <stdint.h>

#define N_Q   4096
#define M_P   32768
#define W_F   768
#define K_NN  4
#define R2    0.25f
#define K_TOT (K_NN * W_F)        // 3072
#define IDX_SENT 0x7FFFFFFF

#define GRID_D 20                  // cells per axis (cell = 0.5 >= radius)
#define NCELL  (GRID_D * GRID_D * GRID_D)   // 8000

// ---------------- scratch (static device memory; no allocs allowed) --------
__device__ int            g_idx[N_Q * K_NN];
__device__ float          g_aggraw[N_Q * W_F];
__device__ int            g_cellcnt[NCELL];
__device__ int            g_cellfill[NCELL];
__device__ int            g_cellstart[NCELL + 1];
__device__ float4         g_binpts[M_P];       // binned {x,y,z,pp}
__device__ int            g_binidx[M_P];       // original point index
__device__ __nv_bfloat16  g_Ah[(size_t)N_Q * K_TOT];
__device__ __nv_bfloat16  g_Al[(size_t)N_Q * K_TOT];
__device__ __nv_bfloat16  g_Bh[(size_t)K_TOT * W_F];
__device__ __nv_bfloat16  g_Bl[(size_t)K_TOT * W_F];

__device__ __forceinline__ bool pair_less(float d1, int i1, float d2, int i2) {
    return (d1 < d2) || (d1 == d2 && i1 < i2);
}

__device__ __forceinline__ uint32_t smem_u32(const void* p) {
    uint32_t a;
    asm("{ .reg .u64 t; cvta.to.shared.u64 t, %1; cvt.u32.u64 %0, t; }"
        : "=r"(a) : "l"(p));
    return a;
}

__device__ __forceinline__ int cell_of(float x, float y, float z) {
    int cx = (int)(x * 2.0f); cx = cx < 0 ? 0 : (cx > GRID_D - 1 ? GRID_D - 1 : cx);
    int cy = (int)(y * 2.0f); cy = cy < 0 ? 0 : (cy > GRID_D - 1 ? GRID_D - 1 : cy);
    int cz = (int)(z * 2.0f); cz = cz < 0 ? 0 : (cz > GRID_D - 1 ? GRID_D - 1 : cz);
    return cx + GRID_D * (cy + GRID_D * cz);
}

// ---------------------------------------------------------------------------
// Grid build: zero -> histogram -> scan -> scatter
// ---------------------------------------------------------------------------
__global__ __launch_bounds__(256) void zero_kernel() {
    const int i = blockIdx.x * 256 + threadIdx.x;
    if (i < NCELL) { g_cellcnt[i] = 0; g_cellfill[i] = 0; }
}

__global__ __launch_bounds__(256) void hist_kernel(const float* __restrict__ pts) {
    const int j = blockIdx.x * 256 + threadIdx.x;
    if (j < M_P) {
        const int c = cell_of(pts[j * 3 + 0], pts[j * 3 + 1], pts[j * 3 + 2]);
        atomicAdd(&g_cellcnt[c], 1);
    }
}

__global__ __launch_bounds__(1024) void scan_kernel() {
    __shared__ int part[1024];
    const int tid  = threadIdx.x;
    const int base = tid * 8;
    int pre[8];
    int sum = 0;
    #pragma unroll
    for (int i = 0; i < 8; i++) {
        const int idx = base + i;
        const int v = (idx < NCELL) ? g_cellcnt[idx] : 0;
        pre[i] = sum;
        sum += v;
    }
    part[tid] = sum;
    __syncthreads();
    for (int off = 1; off < 1024; off <<= 1) {
        int v = (tid >= off) ? part[tid - off] : 0;
        __syncthreads();
        part[tid] += v;
        __syncthreads();
    }
    const int offset = part[tid] - sum;    // exclusive prefix for this thread
    #pragma unroll
    for (int i = 0; i < 8; i++) {
        const int idx = base + i;
        if (idx < NCELL) g_cellstart[idx] = offset + pre[i];
    }
    if (tid == 1023) g_cellstart[NCELL] = part[1023];
}

// scatter: pp computed in the exact reference association (descending FMA).
__global__ __launch_bounds__(256) void scatter_kernel(const float* __restrict__ pts) {
    const int j = blockIdx.x * 256 + threadIdx.x;
    if (j < M_P) {
        const float px = pts[j * 3 + 0];
        const float py = pts[j * 3 + 1];
        const float pz = pts[j * 3 + 2];
        const float pp = __fmaf_rn(px, px, __fmaf_rn(py, py, __fmul_rn(pz, pz)));
        const int c = cell_of(px, py, pz);
        const int slot = g_cellstart[c] + atomicAdd(&g_cellfill[c], 1);
        g_binpts[slot] = make_float4(px, py, pz, pp);
        g_binidx[slot] = j;
    }
}

// ---------------------------------------------------------------------------
// Kernel 1: top-4 NN via grid — one thread per query, ~108 candidate evals.
// Arithmetic FROZEN (R5 bit-exact); selection order-independent under the
// strict total order pair_less, so scatter order is irrelevant.
// ---------------------------------------------------------------------------
__global__ __launch_bounds__(256) void topk_grid_kernel(const float* __restrict__ q_pos) {
    const int n = blockIdx.x * 256 + threadIdx.x;
    if (n >= N_Q) return;

    const float qx = q_pos[n * 3 + 0];
    const float qy = q_pos[n * 3 + 1];
    const float qz = q_pos[n * 3 + 2];
    const float qq = __fmaf_rn(qx, qx, __fmaf_rn(qy, qy, __fmul_rn(qz, qz)));

    int cx = (int)(qx * 2.0f); cx = cx < 0 ? 0 : (cx > GRID_D - 1 ? GRID_D - 1 : cx);
    int cy = (int)(qy * 2.0f); cy = cy < 0 ? 0 : (cy > GRID_D - 1 ? GRID_D - 1 : cy);
    int cz = (int)(qz * 2.0f); cz = cz < 0 ? 0 : (cz > GRID_D - 1 ? GRID_D - 1 : cz);

    const int xlo = cx > 0 ? cx - 1 : 0, xhi = cx < GRID_D - 1 ? cx + 1 : GRID_D - 1;
    const int ylo = cy > 0 ? cy - 1 : 0, yhi = cy < GRID_D - 1 ? cy + 1 : GRID_D - 1;
    const int zlo = cz > 0 ? cz - 1 : 0, zhi = cz < GRID_D - 1 ? cz + 1 : GRID_D - 1;

    float bd[4] = {R2, R2, R2, R2};
    int   bi[4] = {IDX_SENT, IDX_SENT, IDX_SENT, IDX_SENT};

    for (int z = zlo; z <= zhi; z++) {
        for (int y = ylo; y <= yhi; y++) {
            const int crow = GRID_D * (y + GRID_D * z);
            const int s0 = g_cellstart[crow + xlo];
            const int s1 = g_cellstart[crow + xhi + 1];   // x-cells contiguous
            for (int s = s0; s < s1; s++) {
                const float4 p = g_binpts[s];
                const int    j = g_binidx[s];
                float dot = __fmul_rn(qx, p.x);
                dot = __fmaf_rn(qy, p.y, dot);
                dot = __fmaf_rn(qz, p.z, dot);
                const float t1 = __fadd_rn(qq, p.w);
                const float d2 = __fadd_rn(t1, -__fmul_rn(2.0f, dot));
                if (d2 <= bd[3]) {
                    if (pair_less(d2, j, bd[3], bi[3])) {
                        bd[3] = d2; bi[3] = j;
                        #pragma unroll
                        for (int q = 3; q > 0; --q) {
                            if (pair_less(bd[q], bi[q], bd[q - 1], bi[q - 1])) {
                                float td = bd[q]; bd[q] = bd[q - 1]; bd[q - 1] = td;
                                int   ti = bi[q]; bi[q] = bi[q - 1]; bi[q - 1] = ti;
                            }
                        }
                    }
                }
            }
        }
    }

    #pragma unroll
    for (int k = 0; k < 4; k++)
        g_idx[n * 4 + k] = (bi[k] == IDX_SENT) ? -1 : bi[k];
}

// ---------------------------------------------------------------------------
// bf16 split: x = hi + lo (+ ~2^-17 residual)
// ---------------------------------------------------------------------------
__device__ __forceinline__ void bf16_split(float x, __nv_bfloat16& hi, __nv_bfloat16& lo) {
    hi = __float2bfloat16_rn(x);
    lo = __float2bfloat16_rn(x - __bfloat162float(hi));
}

// ---------------------------------------------------------------------------
// Kernel 2a: elementwise split Wagg[3072][768] -> g_Bh/g_Bl
// ---------------------------------------------------------------------------
__global__ __launch_bounds__(256) void wsplit_kernel(const float* __restrict__ Wagg) {
    const size_t id = (size_t)blockIdx.x * 256 + threadIdx.x;
    const float4 v = reinterpret_cast<const float4*>(Wagg)[id];
    __nv_bfloat16 h0,h1,h2,h3,l0,l1,l2,l3;
    bf16_split(v.x, h0, l0);
    bf16_split(v.y, h1, l1);
    bf16_split(v.z, h2, l2);
    bf16_split(v.w, h3, l3);
    __nv_bfloat162* ph = reinterpret_cast<__nv_bfloat162*>(g_Bh) + id * 2;
    __nv_bfloat162* pl = reinterpret_cast<__nv_bfloat162*>(g_Bl) + id * 2;
    ph[0] = __nv_bfloat162(h0, h1);
    ph[1] = __nv_bfloat162(h2, h3);
    pl[0] = __nv_bfloat162(l0, l1);
    pl[1] = __nv_bfloat162(l2, l3);
}

// ---------------------------------------------------------------------------
// Kernel 2b: gather + split feats -> g_Ah/g_Al [4096][3072]
// ---------------------------------------------------------------------------
__global__ __launch_bounds__(256) void gather_kernel(const float* __restrict__ feats) {
    const int n = blockIdx.x;
    __shared__ int sl[4];
    if (threadIdx.x < 4) sl[threadIdx.x] = g_idx[n * 4 + threadIdx.x];
    __syncthreads();

    #pragma unroll
    for (int k = 0; k < 4; k++) {
        const int prow = sl[k];
        const int t = threadIdx.x;
        if (t < 192) {
            float4 v = make_float4(0.f, 0.f, 0.f, 0.f);
            if (prow >= 0)
                v = *reinterpret_cast<const float4*>(&feats[(size_t)prow * W_F + t * 4]);
            __nv_bfloat16 h0,h1,h2,h3,l0,l1,l2,l3;
            bf16_split(v.x, h0, l0);
            bf16_split(v.y, h1, l1);
            bf16_split(v.z, h2, l2);
            bf16_split(v.w, h3, l3);
            const size_t off = (size_t)n * K_TOT + k * W_F + t * 4;
            __nv_bfloat162* ph = reinterpret_cast<__nv_bfloat162*>(&g_Ah[off]);
            __nv_bfloat162* pl = reinterpret_cast<__nv_bfloat162*>(&g_Al[off]);
            ph[0] = __nv_bfloat162(h0, h1);
            ph[1] = __nv_bfloat162(h2, h3);
            pl[0] = __nv_bfloat162(l0, l1);
            pl[1] = __nv_bfloat162(l2, l3);
        }
    }
}

// ---------------------------------------------------------------------------
// Kernel 3: bf16 mma.sync GEMM — C = A·W, 3 plane products, fp32 accum.
// CTA 128x64, K-tile 32, 8 warps, 3-stage cp.async. (at legacy-HMMA roofline)
// ---------------------------------------------------------------------------
#define CTA_M 128
#define CTA_N 64
#define CTA_K 32
#define STAGES 3
#define NKIT (K_TOT / CTA_K)
#define LDA_B 80
#define LDB_B 144
#define A_PLANE_B (CTA_M * LDA_B)
#define B_PLANE_B (CTA_K * LDB_B)
#define STAGE_B (2 * A_PLANE_B + 2 * B_PLANE_B)
#define GEMM_SMEM (STAGES * STAGE_B)

#define CP_ASYNC16(saddr, gaddr) \
    asm volatile("cp.async.cg.shared.global [%0], [%1], 16;" :: "r"(saddr), "l"(gaddr))
#define CP_COMMIT()  asm volatile("cp.async.commit_group;" ::: "memory")
#define CP_WAIT(n)   asm volatile("cp.async.wait_group %0;" :: "n"(n) : "memory")

__device__ __forceinline__ void ldsm_x4(uint32_t& r0, uint32_t& r1, uint32_t& r2,
                                        uint32_t& r3, uint32_t addr) {
    asm volatile("ldmatrix.sync.aligned.m8n8.x4.shared.b16 {%0,%1,%2,%3}, [%4];"
                 : "=r"(r0), "=r"(r1), "=r"(r2), "=r"(r3) : "r"(addr));
}
__device__ __forceinline__ void ldsm_x4_t(uint32_t& r0, uint32_t& r1, uint32_t& r2,
                                          uint32_t& r3, uint32_t addr) {
    asm volatile("ldmatrix.sync.aligned.m8n8.x4.trans.shared.b16 {%0,%1,%2,%3}, [%4];"
                 : "=r"(r0), "=r"(r1), "=r"(r2), "=r"(r3) : "r"(addr));
}
__device__ __forceinline__ void mma16816(float* c, const uint32_t* a, const uint32_t* b) {
    asm volatile(
        "mma.sync.aligned.m16n8k16.row.col.f32.bf16.bf16.f32 "
        "{%0,%1,%2,%3}, {%4,%5,%6,%7}, {%8,%9}, {%0,%1,%2,%3};"
        : "+f"(c[0]), "+f"(c[1]), "+f"(c[2]), "+f"(c[3])
        : "r"(a[0]), "r"(a[1]), "r"(a[2]), "r"(a[3]), "r"(b[0]), "r"(b[1]));
}

__device__ __forceinline__ void load_stage(char* smem, int slot, int kt,
                                           int bm, int bn, int tid) {
    const uint32_t sbase = smem_u32(smem) + (uint32_t)slot * STAGE_B;
    const char* gAh = reinterpret_cast<const char*>(g_Ah);
    const char* gAl = reinterpret_cast<const char*>(g_Al);
    const char* gBh = reinterpret_cast<const char*>(g_Bh);
    const char* gBl = reinterpret_cast<const char*>(g_Bl);

    #pragma unroll
    for (int i = 0; i < 2; i++) {
        const int id  = tid + i * 256;
        const int row = id >> 2;
        const int col = (id & 3) * 16;
        const size_t goff = ((size_t)(bm + row) * K_TOT + kt) * 2 + col;
        CP_ASYNC16(sbase + 0 * A_PLANE_B + row * LDA_B + col, gAh + goff);
        CP_ASYNC16(sbase + 1 * A_PLANE_B + row * LDA_B + col, gAl + goff);
    }
    {
        const int row = tid >> 3;
        const int col = (tid & 7) * 16;
        const size_t goff = ((size_t)(kt + row) * W_F + bn) * 2 + col;
        CP_ASYNC16(sbase + 2 * A_PLANE_B + 0 * B_PLANE_B + row * LDB_B + col, gBh + goff);
        CP_ASYNC16(sbase + 2 * A_PLANE_B + 1 * B_PLANE_B + row * LDB_B + col, gBl + goff);
    }
}

__global__ __launch_bounds__(256) void gemm_mma_kernel(const float* __restrict__ bagg) {
    extern __shared__ char smem[];
    const int tid  = threadIdx.x;
    const int wid  = tid >> 5;
    const int lane = tid & 31;
    const int bm = blockIdx.y * CTA_M;
    const int bn = blockIdx.x * CTA_N;
    const int wm = (wid & 3) * 32;
    const int wn = (wid >> 2) * 32;

    float c[2][4][4];
    #pragma unroll
    for (int mi = 0; mi < 2; mi++)
        #pragma unroll
        for (int ni = 0; ni < 4; ni++)
            #pragma unroll
            for (int r = 0; r < 4; r++) c[mi][ni][r] = 0.0f;

    load_stage(smem, 0, 0, bm, bn, tid); CP_COMMIT();
    load_stage(smem, 1, CTA_K, bm, bn, tid); CP_COMMIT();

    const uint32_t sb = smem_u32(smem);
    const int a_row = wm + (lane & 15);
    const int a_col = (lane >> 4) * 16;
    const int b_row = (lane & 7) + ((lane >> 3) & 1) * 8;
    const int b_col = wn + (lane >> 4) * 8;

    #pragma unroll 1
    for (int it = 0; it < NKIT; it++) {
        CP_WAIT(1);
        __syncthreads();

        if (it + STAGES - 1 < NKIT)
            load_stage(smem, (it + STAGES - 1) % STAGES, (it + STAGES - 1) * CTA_K,
                       bm, bn, tid);
        CP_COMMIT();

        const uint32_t st = sb + (uint32_t)(it % STAGES) * STAGE_B;
        const uint32_t sAh = st;
        const uint32_t sAl = st + A_PLANE_B;
        const uint32_t sBh = st + 2 * A_PLANE_B;
        const uint32_t sBl = sBh + B_PLANE_B;

        #pragma unroll
        for (int k16 = 0; k16 < 2; k16++) {
            uint32_t ah[2][4], al[2][4];
            #pragma unroll
            for (int mi = 0; mi < 2; mi++) {
                const uint32_t off = (uint32_t)((a_row + mi * 16) * LDA_B
                                                + k16 * 32 + a_col);
                ldsm_x4(ah[mi][0], ah[mi][1], ah[mi][2], ah[mi][3], sAh + off);
                ldsm_x4(al[mi][0], al[mi][1], al[mi][2], al[mi][3], sAl + off);
            }
            uint32_t bh[4][2], bl[4][2];
            #pragma unroll
            for (int nh = 0; nh < 2; nh++) {
                const uint32_t off = (uint32_t)((k16 * 16 + b_row) * LDB_B
                                                + (b_col + nh * 16) * 2);
                uint32_t r0, r1, r2, r3;
                ldsm_x4_t(r0, r1, r2, r3, sBh + off);
                bh[nh * 2 + 0][0] = r0; bh[nh * 2 + 0][1] = r1;
                bh[nh * 2 + 1][0] = r2; bh[nh * 2 + 1][1] = r3;
                ldsm_x4_t(r0, r1, r2, r3, sBl + off);
                bl[nh * 2 + 0][0] = r0; bl[nh * 2 + 0][1] = r1;
                bl[nh * 2 + 1][0] = r2; bl[nh * 2 + 1][1] = r3;
            }
            #pragma unroll
            for (int mi = 0; mi < 2; mi++)
                #pragma unroll
                for (int ni = 0; ni < 4; ni++) {
                    mma16816(c[mi][ni], ah[mi], bh[ni]);
                    mma16816(c[mi][ni], ah[mi], bl[ni]);
                    mma16816(c[mi][ni], al[mi], bh[ni]);
                }
        }
        __syncthreads();
    }

    #pragma unroll
    for (int mi = 0; mi < 2; mi++) {
        #pragma unroll
        for (int ni = 0; ni < 4; ni++) {
            const int row0 = bm + wm + mi * 16 + (lane >> 2);
            const int col  = bn + wn + ni * 8 + (lane & 3) * 2;
            const float bx = bagg[col], by = bagg[col + 1];
            float2 o0 = make_float2(c[mi][ni][0] + bx, c[mi][ni][1] + by);
            float2 o1 = make_float2(c[mi][ni][2] + bx, c[mi][ni][3] + by);
            *reinterpret_cast<float2*>(&g_aggraw[(size_t)row0 * W_F + col]) = o0;
            *reinterpret_cast<float2*>(&g_aggraw[(size_t)(row0 + 8) * W_F + col]) = o1;
        }
    }
}

// ---------------------------------------------------------------------------
// Kernel 4: pos embedding GEMV (K=6) + two LayerNorms + add.
// ---------------------------------------------------------------------------
__device__ __forceinline__ float block_sum(float v, float* sbuf) {
    __syncthreads();
    #pragma unroll
    for (int o = 16; o > 0; o >>= 1) v += __shfl_xor_sync(0xffffffffu, v, o);
    const int wid = threadIdx.x >> 5, lane = threadIdx.x & 31;
    if (lane == 0) sbuf[wid] = v;
    __syncthreads();
    if (wid == 0) {
        float x = (lane < 8) ? sbuf[lane] : 0.0f;
        #pragma unroll
        for (int o = 4; o > 0; o >>= 1) x += __shfl_xor_sync(0xffffffffu, x, o);
        if (lane == 0) sbuf[0] = x;
    }
    __syncthreads();
    return sbuf[0];
}

__global__ __launch_bounds__(256) void ln_kernel(const float* __restrict__ pos_in,
                                                 const float* __restrict__ Wpos,
                                                 const float* __restrict__ bpos,
                                                 const float* __restrict__ gagg,
                                                 const float* __restrict__ beagg,
                                                 const float* __restrict__ gpos,
                                                 const float* __restrict__ bepos,
                                                 float* __restrict__ out) {
    const int n   = blockIdx.x;
    const int tid = threadIdx.x;
    __shared__ float pin[6];
    __shared__ float sred[32];
    if (tid < 6) pin[tid] = pos_in[n * 6 + tid];
    __syncthreads();

    float a[3], p[3];
    float sa = 0.f, sp = 0.f;
    #pragma unroll
    for (int t = 0; t < 3; t++) {
        const int j = tid + t * 256;
        a[t] = g_aggraw[n * W_F + j];
        float pv = bpos[j];
        #pragma unroll
        for (int i = 0; i < 6; i++) pv += pin[i] * Wpos[i * W_F + j];
        p[t] = pv;
        sa += a[t]; sp += p[t];
    }
    const float ma = block_sum(sa, sred) * (1.0f / 768.0f);
    const float mp = block_sum(sp, sred) * (1.0f / 768.0f);

    float va = 0.f, vp = 0.f;
    #pragma unroll
    for (int t = 0; t < 3; t++) {
        const float da = a[t] - ma; va += da * da;
        const float dp = p[t] - mp; vp += dp * dp;
    }
    va = block_sum(va, sred) * (1.0f / 768.0f);
    vp = block_sum(vp, sred) * (1.0f / 768.0f);
    const float inva = rsqrtf(va + 1e-12f);
    const float invp = rsqrtf(vp + 1e-12f);

    #pragma unroll
    for (int t = 0; t < 3; t++) {
        const int j = tid + t * 256;
        out[n * W_F + j] = (a[t] - ma) * inva * gagg[j] + beagg[j]
                         + (p[t] - mp) * invp * gpos[j] + bepos[j];
    }
}

// ---------------------------------------------------------------------------
extern "C" void kernel_launch(void* const* d_in, const int* in_sizes, int n_in,
                              void* d_out, int out_size) {
    const float* q_pos  = (const float*)d_in[0];
    const float* pts    = (const float*)d_in[1];
    const float* feats  = (const float*)d_in[2];
    const float* pos_in = (const float*)d_in[3];
    const float* Wagg   = (const float*)d_in[4];
    const float* bagg   = (const float*)d_in[5];
    const float* gagg   = (const float*)d_in[6];
    const float* beagg  = (const float*)d_in[7];
    const float* Wpos   = (const float*)d_in[8];
    const float* bpos   = (const float*)d_in[9];
    const float* gpos   = (const float*)d_in[10];
    const float* bepos  = (const float*)d_in[11];
    float* out = (float*)d_out;

    static int smem_set = 0;
    if (!smem_set) {
        cudaFuncSetAttribute(gemm_mma_kernel,
                             cudaFuncAttributeMaxDynamicSharedMemorySize, GEMM_SMEM);
        smem_set = 1;
    }

    // spatial-grid kNN path
    zero_kernel<<<(NCELL + 255) / 256, 256>>>();
    hist_kernel<<<(M_P + 255) / 256, 256>>>(pts);
    scan_kernel<<<1, 1024>>>();
    scatter_kernel<<<(M_P + 255) / 256, 256>>>(pts);
    topk_grid_kernel<<<(N_Q + 255) / 256, 256>>>(q_pos);

    wsplit_kernel<<<(K_TOT * W_F / 4) / 256, 256>>>(Wagg);
    gather_kernel<<<N_Q, 256>>>(feats);

    dim3 ggrid(W_F / CTA_N, N_Q / CTA_M);            // 12 x 32 = 384 CTAs
    gemm_mma_kernel<<<ggrid, 256, GEMM_SMEM>>>(bagg);

    ln_kernel<<<N_Q, 256>>>(pos_in, Wpos, bpos, gagg, beagg, gpos, bepos, out);
}

// round 12
// speedup vs baseline: 1.8748x; 1.0654x over previous
#include <cuda_runtime.h>
#include <cuda_bf16.h>
#include <float.h>
#include <stdint.h>

#define N_Q   4096
#define M_P   32768
#define W_F   768
#define K_NN  4
#define R2    0.25f
#define K_TOT (K_NN * W_F)        // 3072
#define IDX_SENT 0x7FFFFFFF

#define GRID_D 20                  // cells per axis (cell = 0.5 >= radius)
#define NCELL  (GRID_D * GRID_D * GRID_D)   // 8000

// ---------------- scratch (static device memory; no allocs allowed) --------
__device__ int            g_idx[N_Q * K_NN];
__device__ float          g_aggraw[N_Q * W_F];
__device__ int            g_cellcnt[NCELL];
__device__ int            g_cellfill[NCELL];
__device__ int            g_cellstart[NCELL + 1];
__device__ float4         g_binpts[M_P];       // binned {x,y,z,pp}
__device__ int            g_binidx[M_P];       // original point index
__device__ __nv_bfloat16  g_Ah[(size_t)N_Q * K_TOT];
__device__ __nv_bfloat16  g_Al[(size_t)N_Q * K_TOT];
__device__ __nv_bfloat16  g_Bh[(size_t)K_TOT * W_F];
__device__ __nv_bfloat16  g_Bl[(size_t)K_TOT * W_F];

__device__ __forceinline__ bool pair_less(float d1, int i1, float d2, int i2) {
    return (d1 < d2) || (d1 == d2 && i1 < i2);
}

__device__ __forceinline__ uint32_t smem_u32(const void* p) {
    uint32_t a;
    asm("{ .reg .u64 t; cvta.to.shared.u64 t, %1; cvt.u32.u64 %0, t; }"
        : "=r"(a) : "l"(p));
    return a;
}

__device__ __forceinline__ int cell_of(float x, float y, float z) {
    int cx = (int)(x * 2.0f); cx = cx < 0 ? 0 : (cx > GRID_D - 1 ? GRID_D - 1 : cx);
    int cy = (int)(y * 2.0f); cy = cy < 0 ? 0 : (cy > GRID_D - 1 ? GRID_D - 1 : cy);
    int cz = (int)(z * 2.0f); cz = cz < 0 ? 0 : (cz > GRID_D - 1 ? GRID_D - 1 : cz);
    return cx + GRID_D * (cy + GRID_D * cz);
}

// ---------------------------------------------------------------------------
// Grid build: zero -> histogram -> scan -> scatter
// ---------------------------------------------------------------------------
__global__ __launch_bounds__(256) void zero_kernel() {
    const int i = blockIdx.x * 256 + threadIdx.x;
    if (i < NCELL) { g_cellcnt[i] = 0; g_cellfill[i] = 0; }
}

__global__ __launch_bounds__(256) void hist_kernel(const float* __restrict__ pts) {
    const int j = blockIdx.x * 256 + threadIdx.x;
    if (j < M_P) {
        const int c = cell_of(pts[j * 3 + 0], pts[j * 3 + 1], pts[j * 3 + 2]);
        atomicAdd(&g_cellcnt[c], 1);
    }
}

__global__ __launch_bounds__(1024) void scan_kernel() {
    __shared__ int part[1024];
    const int tid  = threadIdx.x;
    const int base = tid * 8;
    int pre[8];
    int sum = 0;
    #pragma unroll
    for (int i = 0; i < 8; i++) {
        const int idx = base + i;
        const int v = (idx < NCELL) ? g_cellcnt[idx] : 0;
        pre[i] = sum;
        sum += v;
    }
    part[tid] = sum;
    __syncthreads();
    for (int off = 1; off < 1024; off <<= 1) {
        int v = (tid >= off) ? part[tid - off] : 0;
        __syncthreads();
        part[tid] += v;
        __syncthreads();
    }
    const int offset = part[tid] - sum;
    #pragma unroll
    for (int i = 0; i < 8; i++) {
        const int idx = base + i;
        if (idx < NCELL) g_cellstart[idx] = offset + pre[i];
    }
    if (tid == 1023) g_cellstart[NCELL] = part[1023];
}

__global__ __launch_bounds__(256) void scatter_kernel(const float* __restrict__ pts) {
    const int j = blockIdx.x * 256 + threadIdx.x;
    if (j < M_P) {
        const float px = pts[j * 3 + 0];
        const float py = pts[j * 3 + 1];
        const float pz = pts[j * 3 + 2];
        const float pp = __fmaf_rn(px, px, __fmaf_rn(py, py, __fmul_rn(pz, pz)));
        const int c = cell_of(px, py, pz);
        const int slot = g_cellstart[c] + atomicAdd(&g_cellfill[c], 1);
        g_binpts[slot] = make_float4(px, py, pz, pp);
        g_binidx[slot] = j;
    }
}

// ---------------------------------------------------------------------------
// Kernel 1: top-4 NN via grid — one thread per query. Arithmetic FROZEN.
// ---------------------------------------------------------------------------
__global__ __launch_bounds__(256) void topk_grid_kernel(const float* __restrict__ q_pos) {
    const int n = blockIdx.x * 256 + threadIdx.x;
    if (n >= N_Q) return;

    const float qx = q_pos[n * 3 + 0];
    const float qy = q_pos[n * 3 + 1];
    const float qz = q_pos[n * 3 + 2];
    const float qq = __fmaf_rn(qx, qx, __fmaf_rn(qy, qy, __fmul_rn(qz, qz)));

    int cx = (int)(qx * 2.0f); cx = cx < 0 ? 0 : (cx > GRID_D - 1 ? GRID_D - 1 : cx);
    int cy = (int)(qy * 2.0f); cy = cy < 0 ? 0 : (cy > GRID_D - 1 ? GRID_D - 1 : cy);
    int cz = (int)(qz * 2.0f); cz = cz < 0 ? 0 : (cz > GRID_D - 1 ? GRID_D - 1 : cz);

    const int xlo = cx > 0 ? cx - 1 : 0, xhi = cx < GRID_D - 1 ? cx + 1 : GRID_D - 1;
    const int ylo = cy > 0 ? cy - 1 : 0, yhi = cy < GRID_D - 1 ? cy + 1 : GRID_D - 1;
    const int zlo = cz > 0 ? cz - 1 : 0, zhi = cz < GRID_D - 1 ? cz + 1 : GRID_D - 1;

    float bd[4] = {R2, R2, R2, R2};
    int   bi[4] = {IDX_SENT, IDX_SENT, IDX_SENT, IDX_SENT};

    for (int z = zlo; z <= zhi; z++) {
        for (int y = ylo; y <= yhi; y++) {
            const int crow = GRID_D * (y + GRID_D * z);
            const int s0 = g_cellstart[crow + xlo];
            const int s1 = g_cellstart[crow + xhi + 1];
            for (int s = s0; s < s1; s++) {
                const float4 p = g_binpts[s];
                const int    j = g_binidx[s];
                float dot = __fmul_rn(qx, p.x);
                dot = __fmaf_rn(qy, p.y, dot);
                dot = __fmaf_rn(qz, p.z, dot);
                const float t1 = __fadd_rn(qq, p.w);
                const float d2 = __fadd_rn(t1, -__fmul_rn(2.0f, dot));
                if (d2 <= bd[3]) {
                    if (pair_less(d2, j, bd[3], bi[3])) {
                        bd[3] = d2; bi[3] = j;
                        #pragma unroll
                        for (int q = 3; q > 0; --q) {
                            if (pair_less(bd[q], bi[q], bd[q - 1], bi[q - 1])) {
                                float td = bd[q]; bd[q] = bd[q - 1]; bd[q - 1] = td;
                                int   ti = bi[q]; bi[q] = bi[q - 1]; bi[q - 1] = ti;
                            }
                        }
                    }
                }
            }
        }
    }

    #pragma unroll
    for (int k = 0; k < 4; k++)
        g_idx[n * 4 + k] = (bi[k] == IDX_SENT) ? -1 : bi[k];
}

// ---------------------------------------------------------------------------
// bf16 split: x = hi + lo (+ ~2^-17 residual)
// ---------------------------------------------------------------------------
__device__ __forceinline__ void bf16_split(float x, __nv_bfloat16& hi, __nv_bfloat16& lo) {
    hi = __float2bfloat16_rn(x);
    lo = __float2bfloat16_rn(x - __bfloat162float(hi));
}

// ---------------------------------------------------------------------------
// Kernel 2a: elementwise split Wagg[3072][768] -> g_Bh/g_Bl
// ---------------------------------------------------------------------------
__global__ __launch_bounds__(256) void wsplit_kernel(const float* __restrict__ Wagg) {
    const size_t id = (size_t)blockIdx.x * 256 + threadIdx.x;
    const float4 v = reinterpret_cast<const float4*>(Wagg)[id];
    __nv_bfloat16 h0,h1,h2,h3,l0,l1,l2,l3;
    bf16_split(v.x, h0, l0);
    bf16_split(v.y, h1, l1);
    bf16_split(v.z, h2, l2);
    bf16_split(v.w, h3, l3);
    __nv_bfloat162* ph = reinterpret_cast<__nv_bfloat162*>(g_Bh) + id * 2;
    __nv_bfloat162* pl = reinterpret_cast<__nv_bfloat162*>(g_Bl) + id * 2;
    ph[0] = __nv_bfloat162(h0, h1);
    ph[1] = __nv_bfloat162(h2, h3);
    pl[0] = __nv_bfloat162(l0, l1);
    pl[1] = __nv_bfloat162(l2, l3);
}

// ---------------------------------------------------------------------------
// Kernel 2b: gather + split feats -> g_Ah/g_Al [4096][3072]
// ---------------------------------------------------------------------------
__global__ __launch_bounds__(256) void gather_kernel(const float* __restrict__ feats) {
    const int n = blockIdx.x;
    __shared__ int sl[4];
    if (threadIdx.x < 4) sl[threadIdx.x] = g_idx[n * 4 + threadIdx.x];
    __syncthreads();

    #pragma unroll
    for (int k = 0; k < 4; k++) {
        const int prow = sl[k];
        const int t = threadIdx.x;
        if (t < 192) {
            float4 v = make_float4(0.f, 0.f, 0.f, 0.f);
            if (prow >= 0)
                v = *reinterpret_cast<const float4*>(&feats[(size_t)prow * W_F + t * 4]);
            __nv_bfloat16 h0,h1,h2,h3,l0,l1,l2,l3;
            bf16_split(v.x, h0, l0);
            bf16_split(v.y, h1, l1);
            bf16_split(v.z, h2, l2);
            bf16_split(v.w, h3, l3);
            const size_t off = (size_t)n * K_TOT + k * W_F + t * 4;
            __nv_bfloat162* ph = reinterpret_cast<__nv_bfloat162*>(&g_Ah[off]);
            __nv_bfloat162* pl = reinterpret_cast<__nv_bfloat162*>(&g_Al[off]);
            ph[0] = __nv_bfloat162(h0, h1);
            ph[1] = __nv_bfloat162(h2, h3);
            pl[0] = __nv_bfloat162(l0, l1);
            pl[1] = __nv_bfloat162(l2, l3);
        }
    }
}

// ---------------------------------------------------------------------------
// Kernel 3: bf16 mma.sync GEMM — C = A·W, 3 plane products, fp32 accum.
// CTA 128x64, K-tile 32, 8 warps. NOW: 2-stage cp.async + 3 CTAs/SM
// (single resident wave of 384 CTAs, kills wave quantization + stall exposure)
// ---------------------------------------------------------------------------
#define CTA_M 128
#define CTA_N 64
#define CTA_K 32
#define STAGES 2
#define NKIT (K_TOT / CTA_K)
#define LDA_B 80
#define LDB_B 144
#define A_PLANE_B (CTA_M * LDA_B)
#define B_PLANE_B (CTA_K * LDB_B)
#define STAGE_B (2 * A_PLANE_B + 2 * B_PLANE_B)
#define GEMM_SMEM (STAGES * STAGE_B)        // 59392

#define CP_ASYNC16(saddr, gaddr) \
    asm volatile("cp.async.cg.shared.global [%0], [%1], 16;" :: "r"(saddr), "l"(gaddr))
#define CP_COMMIT()  asm volatile("cp.async.commit_group;" ::: "memory")
#define CP_WAIT(n)   asm volatile("cp.async.wait_group %0;" :: "n"(n) : "memory")

__device__ __forceinline__ void ldsm_x4(uint32_t& r0, uint32_t& r1, uint32_t& r2,
                                        uint32_t& r3, uint32_t addr) {
    asm volatile("ldmatrix.sync.aligned.m8n8.x4.shared.b16 {%0,%1,%2,%3}, [%4];"
                 : "=r"(r0), "=r"(r1), "=r"(r2), "=r"(r3) : "r"(addr));
}
__device__ __forceinline__ void ldsm_x4_t(uint32_t& r0, uint32_t& r1, uint32_t& r2,
                                          uint32_t& r3, uint32_t addr) {
    asm volatile("ldmatrix.sync.aligned.m8n8.x4.trans.shared.b16 {%0,%1,%2,%3}, [%4];"
                 : "=r"(r0), "=r"(r1), "=r"(r2), "=r"(r3) : "r"(addr));
}
__device__ __forceinline__ void mma16816(float* c, const uint32_t* a, const uint32_t* b) {
    asm volatile(
        "mma.sync.aligned.m16n8k16.row.col.f32.bf16.bf16.f32 "
        "{%0,%1,%2,%3}, {%4,%5,%6,%7}, {%8,%9}, {%0,%1,%2,%3};"
        : "+f"(c[0]), "+f"(c[1]), "+f"(c[2]), "+f"(c[3])
        : "r"(a[0]), "r"(a[1]), "r"(a[2]), "r"(a[3]), "r"(b[0]), "r"(b[1]));
}

__device__ __forceinline__ void load_stage(char* smem, int slot, int kt,
                                           int bm, int bn, int tid) {
    const uint32_t sbase = smem_u32(smem) + (uint32_t)slot * STAGE_B;
    const char* gAh = reinterpret_cast<const char*>(g_Ah);
    const char* gAl = reinterpret_cast<const char*>(g_Al);
    const char* gBh = reinterpret_cast<const char*>(g_Bh);
    const char* gBl = reinterpret_cast<const char*>(g_Bl);

    #pragma unroll
    for (int i = 0; i < 2; i++) {
        const int id  = tid + i * 256;
        const int row = id >> 2;
        const int col = (id & 3) * 16;
        const size_t goff = ((size_t)(bm + row) * K_TOT + kt) * 2 + col;
        CP_ASYNC16(sbase + 0 * A_PLANE_B + row * LDA_B + col, gAh + goff);
        CP_ASYNC16(sbase + 1 * A_PLANE_B + row * LDA_B + col, gAl + goff);
    }
    {
        const int row = tid >> 3;
        const int col = (tid & 7) * 16;
        const size_t goff = ((size_t)(kt + row) * W_F + bn) * 2 + col;
        CP_ASYNC16(sbase + 2 * A_PLANE_B + 0 * B_PLANE_B + row * LDB_B + col, gBh + goff);
        CP_ASYNC16(sbase + 2 * A_PLANE_B + 1 * B_PLANE_B + row * LDB_B + col, gBl + goff);
    }
}

__global__ __launch_bounds__(256, 3) void gemm_mma_kernel(const float* __restrict__ bagg) {
    extern __shared__ char smem[];
    const int tid  = threadIdx.x;
    const int wid  = tid >> 5;
    const int lane = tid & 31;
    const int bm = blockIdx.y * CTA_M;
    const int bn = blockIdx.x * CTA_N;
    const int wm = (wid & 3) * 32;
    const int wn = (wid >> 2) * 32;

    float c[2][4][4];
    #pragma unroll
    for (int mi = 0; mi < 2; mi++)
        #pragma unroll
        for (int ni = 0; ni < 4; ni++)
            #pragma unroll
            for (int r = 0; r < 4; r++) c[mi][ni][r] = 0.0f;

    load_stage(smem, 0, 0, bm, bn, tid); CP_COMMIT();

    const uint32_t sb = smem_u32(smem);
    const int a_row = wm + (lane & 15);
    const int a_col = (lane >> 4) * 16;
    const int b_row = (lane & 7) + ((lane >> 3) & 1) * 8;
    const int b_col = wn + (lane >> 4) * 8;

    #pragma unroll 1
    for (int it = 0; it < NKIT; it++) {
        // issue next stage (slot was last consumed in iter it-1; trailing sync protects)
        if (it + 1 < NKIT)
            load_stage(smem, (it + 1) & 1, (it + 1) * CTA_K, bm, bn, tid);
        CP_COMMIT();                 // unconditional: keeps wait_group(1) correct at tail
        CP_WAIT(1);                  // stage 'it' resident; stage it+1 in flight
        __syncthreads();

        const uint32_t st = sb + (uint32_t)(it & 1) * STAGE_B;
        const uint32_t sAh = st;
        const uint32_t sAl = st + A_PLANE_B;
        const uint32_t sBh = st + 2 * A_PLANE_B;
        const uint32_t sBl = sBh + B_PLANE_B;

        #pragma unroll
        for (int k16 = 0; k16 < 2; k16++) {
            uint32_t ah[2][4], al[2][4];
            #pragma unroll
            for (int mi = 0; mi < 2; mi++) {
                const uint32_t off = (uint32_t)((a_row + mi * 16) * LDA_B
                                                + k16 * 32 + a_col);
                ldsm_x4(ah[mi][0], ah[mi][1], ah[mi][2], ah[mi][3], sAh + off);
                ldsm_x4(al[mi][0], al[mi][1], al[mi][2], al[mi][3], sAl + off);
            }
            uint32_t bh[4][2], bl[4][2];
            #pragma unroll
            for (int nh = 0; nh < 2; nh++) {
                const uint32_t off = (uint32_t)((k16 * 16 + b_row) * LDB_B
                                                + (b_col + nh * 16) * 2);
                uint32_t r0, r1, r2, r3;
                ldsm_x4_t(r0, r1, r2, r3, sBh + off);
                bh[nh * 2 + 0][0] = r0; bh[nh * 2 + 0][1] = r1;
                bh[nh * 2 + 1][0] = r2; bh[nh * 2 + 1][1] = r3;
                ldsm_x4_t(r0, r1, r2, r3, sBl + off);
                bl[nh * 2 + 0][0] = r0; bl[nh * 2 + 0][1] = r1;
                bl[nh * 2 + 1][0] = r2; bl[nh * 2 + 1][1] = r3;
            }
            #pragma unroll
            for (int mi = 0; mi < 2; mi++)
                #pragma unroll
                for (int ni = 0; ni < 4; ni++) {
                    mma16816(c[mi][ni], ah[mi], bh[ni]);
                    mma16816(c[mi][ni], ah[mi], bl[ni]);
                    mma16816(c[mi][ni], al[mi], bh[ni]);
                }
        }
        __syncthreads();             // all reads of slot it&1 done before overwrite
    }

    #pragma unroll
    for (int mi = 0; mi < 2; mi++) {
        #pragma unroll
        for (int ni = 0; ni < 4; ni++) {
            const int row0 = bm + wm + mi * 16 + (lane >> 2);
            const int col  = bn + wn + ni * 8 + (lane & 3) * 2;
            const float bx = bagg[col], by = bagg[col + 1];
            float2 o0 = make_float2(c[mi][ni][0] + bx, c[mi][ni][1] + by);
            float2 o1 = make_float2(c[mi][ni][2] + bx, c[mi][ni][3] + by);
            *reinterpret_cast<float2*>(&g_aggraw[(size_t)row0 * W_F + col]) = o0;
            *reinterpret_cast<float2*>(&g_aggraw[(size_t)(row0 + 8) * W_F + col]) = o1;
        }
    }
}

// ---------------------------------------------------------------------------
// Kernel 4: warp-per-row pos GEMV + two LayerNorms + add. 8 rows per block.
// ---------------------------------------------------------------------------
__global__ __launch_bounds__(256) void ln_kernel(const float* __restrict__ pos_in,
                                                 const float* __restrict__ Wpos,
                                                 const float* __restrict__ bpos,
                                                 const float* __restrict__ gagg,
                                                 const float* __restrict__ beagg,
                                                 const float* __restrict__ gpos,
                                                 const float* __restrict__ bepos,
                                                 float* __restrict__ out) {
    const int wid  = threadIdx.x >> 5;
    const int lane = threadIdx.x & 31;
    const int n    = blockIdx.x * 8 + wid;

    float pin[6];
    #pragma unroll
    for (int i = 0; i < 6; i++) pin[i] = pos_in[n * 6 + i];

    float a[24], p[24];
    float sa = 0.f, sp = 0.f;
    #pragma unroll
    for (int t = 0; t < 24; t++) {
        const int j = lane + t * 32;
        a[t] = g_aggraw[(size_t)n * W_F + j];
        float pv = bpos[j];
        #pragma unroll
        for (int i = 0; i < 6; i++) pv += pin[i] * Wpos[i * W_F + j];
        p[t] = pv;
        sa += a[t]; sp += p[t];
    }
    #pragma unroll
    for (int o = 16; o > 0; o >>= 1) {
        sa += __shfl_xor_sync(0xffffffffu, sa, o);
        sp += __shfl_xor_sync(0xffffffffu, sp, o);
    }
    const float ma = sa * (1.0f / 768.0f);
    const float mp = sp * (1.0f / 768.0f);

    float va = 0.f, vp = 0.f;
    #pragma unroll
    for (int t = 0; t < 24; t++) {
        const float da = a[t] - ma; va += da * da;
        const float dp = p[t] - mp; vp += dp * dp;
    }
    #pragma unroll
    for (int o = 16; o > 0; o >>= 1) {
        va += __shfl_xor_sync(0xffffffffu, va, o);
        vp += __shfl_xor_sync(0xffffffffu, vp, o);
    }
    const float inva = rsqrtf(va * (1.0f / 768.0f) + 1e-12f);
    const float invp = rsqrtf(vp * (1.0f / 768.0f) + 1e-12f);

    #pragma unroll
    for (int t = 0; t < 24; t++) {
        const int j = lane + t * 32;
        out[(size_t)n * W_F + j] = (a[t] - ma) * inva * gagg[j] + beagg[j]
                                 + (p[t] - mp) * invp * gpos[j] + bepos[j];
    }
}

// ---------------------------------------------------------------------------
extern "C" void kernel_launch(void* const* d_in, const int* in_sizes, int n_in,
                              void* d_out, int out_size) {
    const float* q_pos  = (const float*)d_in[0];
    const float* pts    = (const float*)d_in[1];
    const float* feats  = (const float*)d_in[2];
    const float* pos_in = (const float*)d_in[3];
    const float* Wagg   = (const float*)d_in[4];
    const float* bagg   = (const float*)d_in[5];
    const float* gagg   = (const float*)d_in[6];
    const float* beagg  = (const float*)d_in[7];
    const float* Wpos   = (const float*)d_in[8];
    const float* bpos   = (const float*)d_in[9];
    const float* gpos   = (const float*)d_in[10];
    const float* bepos  = (const float*)d_in[11];
    float* out = (float*)d_out;

    static int smem_set = 0;
    if (!smem_set) {
        cudaFuncSetAttribute(gemm_mma_kernel,
                             cudaFuncAttributeMaxDynamicSharedMemorySize, GEMM_SMEM);
        smem_set = 1;
    }

    // spatial-grid kNN path
    zero_kernel<<<(NCELL + 255) / 256, 256>>>();
    hist_kernel<<<(M_P + 255) / 256, 256>>>(pts);
    scan_kernel<<<1, 1024>>>();
    scatter_kernel<<<(M_P + 255) / 256, 256>>>(pts);
    topk_grid_kernel<<<(N_Q + 255) / 256, 256>>>(q_pos);

    wsplit_kernel<<<(K_TOT * W_F / 4) / 256, 256>>>(Wagg);
    gather_kernel<<<N_Q, 256>>>(feats);

    dim3 ggrid(W_F / CTA_N, N_Q / CTA_M);            // 12 x 32 = 384 CTAs
    gemm_mma_kernel<<<ggrid, 256, GEMM_SMEM>>>(bagg);

    ln_kernel<<<N_Q / 8, 256>>>(pos_in, Wpos, bpos, gagg, beagg, gpos, bepos, out);
}

// round 13
// speedup vs baseline: 3.0385x; 1.6207x over previous
#include <cuda_runtime.h>
#include <cuda_fp16.h>
#include <float.h>
#include <stdint.h>

#define N_Q   4096
#define M_P   32768
#define W_F   768
#define K_NN  4
#define R2    0.25f
#define K_TOT (K_NN * W_F)        // 3072
#define IDX_SENT 0x7FFFFFFF

#define GRID_D 20                  // cells per axis (cell = 0.5 >= radius)
#define NCELL  (GRID_D * GRID_D * GRID_D)   // 8000

// ---------------- scratch (static device memory; no allocs allowed) --------
__device__ int      g_idx[N_Q * K_NN];
__device__ float    g_aggraw[N_Q * W_F];
__device__ int      g_cellcnt[NCELL];
__device__ int      g_cellfill[NCELL];
__device__ int      g_cellstart[NCELL + 1];
__device__ float4   g_binpts[M_P];       // binned {x,y,z,pp}
__device__ int      g_binidx[M_P];       // original point index
__device__ __half   g_A[(size_t)N_Q * K_TOT];    // gathered A, fp16
__device__ __half   g_B[(size_t)K_TOT * W_F];    // Wagg, fp16 [3072][768]

__device__ __forceinline__ bool pair_less(float d1, int i1, float d2, int i2) {
    return (d1 < d2) || (d1 == d2 && i1 < i2);
}

__device__ __forceinline__ uint32_t smem_u32(const void* p) {
    uint32_t a;
    asm("{ .reg .u64 t; cvta.to.shared.u64 t, %1; cvt.u32.u64 %0, t; }"
        : "=r"(a) : "l"(p));
    return a;
}

__device__ __forceinline__ int cell_of(float x, float y, float z) {
    int cx = (int)(x * 2.0f); cx = cx < 0 ? 0 : (cx > GRID_D - 1 ? GRID_D - 1 : cx);
    int cy = (int)(y * 2.0f); cy = cy < 0 ? 0 : (cy > GRID_D - 1 ? GRID_D - 1 : cy);
    int cz = (int)(z * 2.0f); cz = cz < 0 ? 0 : (cz > GRID_D - 1 ? GRID_D - 1 : cz);
    return cx + GRID_D * (cy + GRID_D * cz);
}

// ---------------------------------------------------------------------------
// Grid build: zero -> histogram -> scan -> scatter
// ---------------------------------------------------------------------------
__global__ __launch_bounds__(256) void zero_kernel() {
    const int i = blockIdx.x * 256 + threadIdx.x;
    if (i < NCELL) { g_cellcnt[i] = 0; g_cellfill[i] = 0; }
}

__global__ __launch_bounds__(256) void hist_kernel(const float* __restrict__ pts) {
    const int j = blockIdx.x * 256 + threadIdx.x;
    if (j < M_P) {
        const int c = cell_of(pts[j * 3 + 0], pts[j * 3 + 1], pts[j * 3 + 2]);
        atomicAdd(&g_cellcnt[c], 1);
    }
}

__global__ __launch_bounds__(1024) void scan_kernel() {
    __shared__ int part[1024];
    const int tid  = threadIdx.x;
    const int base = tid * 8;
    int pre[8];
    int sum = 0;
    #pragma unroll
    for (int i = 0; i < 8; i++) {
        const int idx = base + i;
        const int v = (idx < NCELL) ? g_cellcnt[idx] : 0;
        pre[i] = sum;
        sum += v;
    }
    part[tid] = sum;
    __syncthreads();
    for (int off = 1; off < 1024; off <<= 1) {
        int v = (tid >= off) ? part[tid - off] : 0;
        __syncthreads();
        part[tid] += v;
        __syncthreads();
    }
    const int offset = part[tid] - sum;
    #pragma unroll
    for (int i = 0; i < 8; i++) {
        const int idx = base + i;
        if (idx < NCELL) g_cellstart[idx] = offset + pre[i];
    }
    if (tid == 1023) g_cellstart[NCELL] = part[1023];
}

__global__ __launch_bounds__(256) void scatter_kernel(const float* __restrict__ pts) {
    const int j = blockIdx.x * 256 + threadIdx.x;
    if (j < M_P) {
        const float px = pts[j * 3 + 0];
        const float py = pts[j * 3 + 1];
        const float pz = pts[j * 3 + 2];
        const float pp = __fmaf_rn(px, px, __fmaf_rn(py, py, __fmul_rn(pz, pz)));
        const int c = cell_of(px, py, pz);
        const int slot = g_cellstart[c] + atomicAdd(&g_cellfill[c], 1);
        g_binpts[slot] = make_float4(px, py, pz, pp);
        g_binidx[slot] = j;
    }
}

// ---------------------------------------------------------------------------
// Kernel 1: top-4 NN via grid — one thread per query. Arithmetic FROZEN.
// ---------------------------------------------------------------------------
__global__ __launch_bounds__(256) void topk_grid_kernel(const float* __restrict__ q_pos) {
    const int n = blockIdx.x * 256 + threadIdx.x;
    if (n >= N_Q) return;

    const float qx = q_pos[n * 3 + 0];
    const float qy = q_pos[n * 3 + 1];
    const float qz = q_pos[n * 3 + 2];
    const float qq = __fmaf_rn(qx, qx, __fmaf_rn(qy, qy, __fmul_rn(qz, qz)));

    int cx = (int)(qx * 2.0f); cx = cx < 0 ? 0 : (cx > GRID_D - 1 ? GRID_D - 1 : cx);
    int cy = (int)(qy * 2.0f); cy = cy < 0 ? 0 : (cy > GRID_D - 1 ? GRID_D - 1 : cy);
    int cz = (int)(qz * 2.0f); cz = cz < 0 ? 0 : (cz > GRID_D - 1 ? GRID_D - 1 : cz);

    const int xlo = cx > 0 ? cx - 1 : 0, xhi = cx < GRID_D - 1 ? cx + 1 : GRID_D - 1;
    const int ylo = cy > 0 ? cy - 1 : 0, yhi = cy < GRID_D - 1 ? cy + 1 : GRID_D - 1;
    const int zlo = cz > 0 ? cz - 1 : 0, zhi = cz < GRID_D - 1 ? cz + 1 : GRID_D - 1;

    float bd[4] = {R2, R2, R2, R2};
    int   bi[4] = {IDX_SENT, IDX_SENT, IDX_SENT, IDX_SENT};

    for (int z = zlo; z <= zhi; z++) {
        for (int y = ylo; y <= yhi; y++) {
            const int crow = GRID_D * (y + GRID_D * z);
            const int s0 = g_cellstart[crow + xlo];
            const int s1 = g_cellstart[crow + xhi + 1];
            for (int s = s0; s < s1; s++) {
                const float4 p = g_binpts[s];
                const int    j = g_binidx[s];
                float dot = __fmul_rn(qx, p.x);
                dot = __fmaf_rn(qy, p.y, dot);
                dot = __fmaf_rn(qz, p.z, dot);
                const float t1 = __fadd_rn(qq, p.w);
                const float d2 = __fadd_rn(t1, -__fmul_rn(2.0f, dot));
                if (d2 <= bd[3]) {
                    if (pair_less(d2, j, bd[3], bi[3])) {
                        bd[3] = d2; bi[3] = j;
                        #pragma unroll
                        for (int q = 3; q > 0; --q) {
                            if (pair_less(bd[q], bi[q], bd[q - 1], bi[q - 1])) {
                                float td = bd[q]; bd[q] = bd[q - 1]; bd[q - 1] = td;
                                int   ti = bi[q]; bi[q] = bi[q - 1]; bi[q - 1] = ti;
                            }
                        }
                    }
                }
            }
        }
    }

    #pragma unroll
    for (int k = 0; k < 4; k++)
        g_idx[n * 4 + k] = (bi[k] == IDX_SENT) ? -1 : bi[k];
}

// ---------------------------------------------------------------------------
// Kernel 2a: convert Wagg[3072][768] -> g_B (fp16)
// ---------------------------------------------------------------------------
__global__ __launch_bounds__(256) void wconv_kernel(const float* __restrict__ Wagg) {
    const size_t id = (size_t)blockIdx.x * 256 + threadIdx.x;   // float4 index
    const float4 v = reinterpret_cast<const float4*>(Wagg)[id];
    __half2* ph = reinterpret_cast<__half2*>(g_B) + id * 2;
    ph[0] = __halves2half2(__float2half_rn(v.x), __float2half_rn(v.y));
    ph[1] = __halves2half2(__float2half_rn(v.z), __float2half_rn(v.w));
}

// ---------------------------------------------------------------------------
// Kernel 2b: gather + convert feats -> g_A [4096][3072] fp16
// ---------------------------------------------------------------------------
__global__ __launch_bounds__(256) void gather_kernel(const float* __restrict__ feats) {
    const int n = blockIdx.x;
    __shared__ int sl[4];
    if (threadIdx.x < 4) sl[threadIdx.x] = g_idx[n * 4 + threadIdx.x];
    __syncthreads();

    #pragma unroll
    for (int k = 0; k < 4; k++) {
        const int prow = sl[k];
        const int t = threadIdx.x;
        if (t < 192) {
            float4 v = make_float4(0.f, 0.f, 0.f, 0.f);
            if (prow >= 0)
                v = *reinterpret_cast<const float4*>(&feats[(size_t)prow * W_F + t * 4]);
            const size_t off = (size_t)n * K_TOT + k * W_F + t * 4;
            __half2* ph = reinterpret_cast<__half2*>(&g_A[off]);
            ph[0] = __halves2half2(__float2half_rn(v.x), __float2half_rn(v.y));
            ph[1] = __halves2half2(__float2half_rn(v.z), __float2half_rn(v.w));
        }
    }
}

// ---------------------------------------------------------------------------
// Kernel 3: fp16 mma.sync GEMM — C = A·W, SINGLE product, fp32 accum.
// CTA 128x64, K-tile 32, 8 warps (4m x 2n), 3-stage cp.async, 3 CTAs/SM.
// ---------------------------------------------------------------------------
#define CTA_M 128
#define CTA_N 64
#define CTA_K 32
#define STAGES 3
#define NKIT (K_TOT / CTA_K)                // 96
#define LDA_B 80                            // 64B data + 16B pad
#define LDB_B 144                           // 128B data + 16B pad
#define A_PLANE_B (CTA_M * LDA_B)           // 10240
#define B_PLANE_B (CTA_K * LDB_B)           // 4608
#define STAGE_B (A_PLANE_B + B_PLANE_B)     // 14848
#define GEMM_SMEM (STAGES * STAGE_B)        // 44544

#define CP_ASYNC16(saddr, gaddr) \
    asm volatile("cp.async.cg.shared.global [%0], [%1], 16;" :: "r"(saddr), "l"(gaddr))
#define CP_COMMIT()  asm volatile("cp.async.commit_group;" ::: "memory")
#define CP_WAIT(n)   asm volatile("cp.async.wait_group %0;" :: "n"(n) : "memory")

__device__ __forceinline__ void ldsm_x4(uint32_t& r0, uint32_t& r1, uint32_t& r2,
                                        uint32_t& r3, uint32_t addr) {
    asm volatile("ldmatrix.sync.aligned.m8n8.x4.shared.b16 {%0,%1,%2,%3}, [%4];"
                 : "=r"(r0), "=r"(r1), "=r"(r2), "=r"(r3) : "r"(addr));
}
__device__ __forceinline__ void ldsm_x4_t(uint32_t& r0, uint32_t& r1, uint32_t& r2,
                                          uint32_t& r3, uint32_t addr) {
    asm volatile("ldmatrix.sync.aligned.m8n8.x4.trans.shared.b16 {%0,%1,%2,%3}, [%4];"
                 : "=r"(r0), "=r"(r1), "=r"(r2), "=r"(r3) : "r"(addr));
}
__device__ __forceinline__ void mma16816_f16(float* c, const uint32_t* a, const uint32_t* b) {
    asm volatile(
        "mma.sync.aligned.m16n8k16.row.col.f32.f16.f16.f32 "
        "{%0,%1,%2,%3}, {%4,%5,%6,%7}, {%8,%9}, {%0,%1,%2,%3};"
        : "+f"(c[0]), "+f"(c[1]), "+f"(c[2]), "+f"(c[3])
        : "r"(a[0]), "r"(a[1]), "r"(a[2]), "r"(a[3]), "r"(b[0]), "r"(b[1]));
}

__device__ __forceinline__ void load_stage(char* smem, int slot, int kt,
                                           int bm, int bn, int tid) {
    const uint32_t sbase = smem_u32(smem) + (uint32_t)slot * STAGE_B;
    const char* gA = reinterpret_cast<const char*>(g_A);
    const char* gB = reinterpret_cast<const char*>(g_B);

    // A: 128 rows x 64B = 512 x 16B chunks; 2 per thread
    #pragma unroll
    for (int i = 0; i < 2; i++) {
        const int id  = tid + i * 256;
        const int row = id >> 2;
        const int col = (id & 3) * 16;
        const size_t goff = ((size_t)(bm + row) * K_TOT + kt) * 2 + col;
        CP_ASYNC16(sbase + row * LDA_B + col, gA + goff);
    }
    // B: 32 rows x 128B = 256 x 16B chunks; 1 per thread
    {
        const int row = tid >> 3;
        const int col = (tid & 7) * 16;
        const size_t goff = ((size_t)(kt + row) * W_F + bn) * 2 + col;
        CP_ASYNC16(sbase + A_PLANE_B + row * LDB_B + col, gB + goff);
    }
}

__global__ __launch_bounds__(256, 3) void gemm_mma_kernel(const float* __restrict__ bagg) {
    extern __shared__ char smem[];
    const int tid  = threadIdx.x;
    const int wid  = tid >> 5;
    const int lane = tid & 31;
    const int bm = blockIdx.y * CTA_M;
    const int bn = blockIdx.x * CTA_N;
    const int wm = (wid & 3) * 32;
    const int wn = (wid >> 2) * 32;

    float c[2][4][4];
    #pragma unroll
    for (int mi = 0; mi < 2; mi++)
        #pragma unroll
        for (int ni = 0; ni < 4; ni++)
            #pragma unroll
            for (int r = 0; r < 4; r++) c[mi][ni][r] = 0.0f;

    load_stage(smem, 0, 0, bm, bn, tid); CP_COMMIT();
    load_stage(smem, 1, CTA_K, bm, bn, tid); CP_COMMIT();

    const uint32_t sb = smem_u32(smem);
    const int a_row = wm + (lane & 15);
    const int a_col = (lane >> 4) * 16;
    const int b_row = (lane & 7) + ((lane >> 3) & 1) * 8;
    const int b_col = wn + (lane >> 4) * 8;

    #pragma unroll 1
    for (int it = 0; it < NKIT; it++) {
        CP_WAIT(1);
        __syncthreads();

        if (it + STAGES - 1 < NKIT)
            load_stage(smem, (it + STAGES - 1) % STAGES, (it + STAGES - 1) * CTA_K,
                       bm, bn, tid);
        CP_COMMIT();

        const uint32_t st = sb + (uint32_t)(it % STAGES) * STAGE_B;
        const uint32_t sA = st;
        const uint32_t sB = st + A_PLANE_B;

        #pragma unroll
        for (int k16 = 0; k16 < 2; k16++) {
            uint32_t a[2][4];
            #pragma unroll
            for (int mi = 0; mi < 2; mi++) {
                const uint32_t off = (uint32_t)((a_row + mi * 16) * LDA_B
                                                + k16 * 32 + a_col);
                ldsm_x4(a[mi][0], a[mi][1], a[mi][2], a[mi][3], sA + off);
            }
            uint32_t b[4][2];
            #pragma unroll
            for (int nh = 0; nh < 2; nh++) {
                const uint32_t off = (uint32_t)((k16 * 16 + b_row) * LDB_B
                                                + (b_col + nh * 16) * 2);
                uint32_t r0, r1, r2, r3;
                ldsm_x4_t(r0, r1, r2, r3, sB + off);
                b[nh * 2 + 0][0] = r0; b[nh * 2 + 0][1] = r1;
                b[nh * 2 + 1][0] = r2; b[nh * 2 + 1][1] = r3;
            }
            #pragma unroll
            for (int mi = 0; mi < 2; mi++)
                #pragma unroll
                for (int ni = 0; ni < 4; ni++)
                    mma16816_f16(c[mi][ni], a[mi], b[ni]);
        }
        __syncthreads();
    }

    #pragma unroll
    for (int mi = 0; mi < 2; mi++) {
        #pragma unroll
        for (int ni = 0; ni < 4; ni++) {
            const int row0 = bm + wm + mi * 16 + (lane >> 2);
            const int col  = bn + wn + ni * 8 + (lane & 3) * 2;
            const float bx = bagg[col], by = bagg[col + 1];
            float2 o0 = make_float2(c[mi][ni][0] + bx, c[mi][ni][1] + by);
            float2 o1 = make_float2(c[mi][ni][2] + bx, c[mi][ni][3] + by);
            *reinterpret_cast<float2*>(&g_aggraw[(size_t)row0 * W_F + col]) = o0;
            *reinterpret_cast<float2*>(&g_aggraw[(size_t)(row0 + 8) * W_F + col]) = o1;
        }
    }
}

// ---------------------------------------------------------------------------
// Kernel 4: warp-per-row pos GEMV + two LayerNorms + add. 8 rows per block.
// ---------------------------------------------------------------------------
__global__ __launch_bounds__(256) void ln_kernel(const float* __restrict__ pos_in,
                                                 const float* __restrict__ Wpos,
                                                 const float* __restrict__ bpos,
                                                 const float* __restrict__ gagg,
                                                 const float* __restrict__ beagg,
                                                 const float* __restrict__ gpos,
                                                 const float* __restrict__ bepos,
                                                 float* __restrict__ out) {
    const int wid  = threadIdx.x >> 5;
    const int lane = threadIdx.x & 31;
    const int n    = blockIdx.x * 8 + wid;

    float pin[6];
    #pragma unroll
    for (int i = 0; i < 6; i++) pin[i] = pos_in[n * 6 + i];

    float a[24], p[24];
    float sa = 0.f, sp = 0.f;
    #pragma unroll
    for (int t = 0; t < 24; t++) {
        const int j = lane + t * 32;
        a[t] = g_aggraw[(size_t)n * W_F + j];
        float pv = bpos[j];
        #pragma unroll
        for (int i = 0; i < 6; i++) pv += pin[i] * Wpos[i * W_F + j];
        p[t] = pv;
        sa += a[t]; sp += p[t];
    }
    #pragma unroll
    for (int o = 16; o > 0; o >>= 1) {
        sa += __shfl_xor_sync(0xffffffffu, sa, o);
        sp += __shfl_xor_sync(0xffffffffu, sp, o);
    }
    const float ma = sa * (1.0f / 768.0f);
    const float mp = sp * (1.0f / 768.0f);

    float va = 0.f, vp = 0.f;
    #pragma unroll
    for (int t = 0; t < 24; t++) {
        const float da = a[t] - ma; va += da * da;
        const float dp = p[t] - mp; vp += dp * dp;
    }
    #pragma unroll
    for (int o = 16; o > 0; o >>= 1) {
        va += __shfl_xor_sync(0xffffffffu, va, o);
        vp += __shfl_xor_sync(0xffffffffu, vp, o);
    }
    const float inva = rsqrtf(va * (1.0f / 768.0f) + 1e-12f);
    const float invp = rsqrtf(vp * (1.0f / 768.0f) + 1e-12f);

    #pragma unroll
    for (int t = 0; t < 24; t++) {
        const int j = lane + t * 32;
        out[(size_t)n * W_F + j] = (a[t] - ma) * inva * gagg[j] + beagg[j]
                                 + (p[t] - mp) * invp * gpos[j] + bepos[j];
    }
}

// ---------------------------------------------------------------------------
extern "C" void kernel_launch(void* const* d_in, const int* in_sizes, int n_in,
                              void* d_out, int out_size) {
    const float* q_pos  = (const float*)d_in[0];
    const float* pts    = (const float*)d_in[1];
    const float* feats  = (const float*)d_in[2];
    const float* pos_in = (const float*)d_in[3];
    const float* Wagg   = (const float*)d_in[4];
    const float* bagg   = (const float*)d_in[5];
    const float* gagg   = (const float*)d_in[6];
    const float* beagg  = (const float*)d_in[7];
    const float* Wpos   = (const float*)d_in[8];
    const float* bpos   = (const float*)d_in[9];
    const float* gpos   = (const float*)d_in[10];
    const float* bepos  = (const float*)d_in[11];
    float* out = (float*)d_out;

    static int smem_set = 0;
    if (!smem_set) {
        cudaFuncSetAttribute(gemm_mma_kernel,
                             cudaFuncAttributeMaxDynamicSharedMemorySize, GEMM_SMEM);
        smem_set = 1;
    }

    // spatial-grid kNN path
    zero_kernel<<<(NCELL + 255) / 256, 256>>>();
    hist_kernel<<<(M_P + 255) / 256, 256>>>(pts);
    scan_kernel<<<1, 1024>>>();
    scatter_kernel<<<(M_P + 255) / 256, 256>>>(pts);
    topk_grid_kernel<<<(N_Q + 255) / 256, 256>>>(q_pos);

    wconv_kernel<<<(K_TOT * W_F / 4) / 256, 256>>>(Wagg);
    gather_kernel<<<N_Q, 256>>>(feats);

    dim3 ggrid(W_F / CTA_N, N_Q / CTA_M);            // 12 x 32 = 384 CTAs
    gemm_mma_kernel<<<ggrid, 256, GEMM_SMEM>>>(bagg);

    ln_kernel<<<N_Q / 8, 256>>>(pos_in, Wpos, bpos, gagg, beagg, gpos, bepos, out);
}

// round 14
// speedup vs baseline: 3.1511x; 1.0370x over previous
#include <cuda_runtime.h>
#include <cuda_fp16.h>
#include <float.h>
#include <stdint.h>

#define N_Q   4096
#define M_P   32768
#define W_F   768
#define K_NN  4
#define R2    0.25f
#define K_TOT (K_NN * W_F)        // 3072
#define IDX_SENT 0x7FFFFFFF

#define GRID_D 20                  // cells per axis (cell = 0.5 >= radius)
#define NCELL  (GRID_D * GRID_D * GRID_D)   // 8000

// ---------------- scratch (static device memory; no allocs allowed) --------
__device__ int      g_idx[N_Q * K_NN];
__device__ float    g_aggraw[N_Q * W_F];
__device__ int      g_cellcnt[NCELL];
__device__ int      g_cellfill[NCELL];
__device__ int      g_cellstart[NCELL + 1];
__device__ float4   g_binpts[M_P];       // binned {x,y,z,pp}
__device__ int      g_binidx[M_P];       // original point index
__device__ __half   g_A[(size_t)N_Q * K_TOT];    // gathered A, fp16
__device__ __half   g_B[(size_t)K_TOT * W_F];    // Wagg, fp16 [3072][768]

__device__ __forceinline__ bool pair_less(float d1, int i1, float d2, int i2) {
    return (d1 < d2) || (d1 == d2 && i1 < i2);
}

__device__ __forceinline__ uint32_t smem_u32(const void* p) {
    uint32_t a;
    asm("{ .reg .u64 t; cvta.to.shared.u64 t, %1; cvt.u32.u64 %0, t; }"
        : "=r"(a) : "l"(p));
    return a;
}

__device__ __forceinline__ int cell_of(float x, float y, float z) {
    int cx = (int)(x * 2.0f); cx = cx < 0 ? 0 : (cx > GRID_D - 1 ? GRID_D - 1 : cx);
    int cy = (int)(y * 2.0f); cy = cy < 0 ? 0 : (cy > GRID_D - 1 ? GRID_D - 1 : cy);
    int cz = (int)(z * 2.0f); cz = cz < 0 ? 0 : (cz > GRID_D - 1 ? GRID_D - 1 : cz);
    return cx + GRID_D * (cy + GRID_D * cz);
}

// ---------------------------------------------------------------------------
// Grid build: zero -> histogram -> scan -> scatter
// ---------------------------------------------------------------------------
__global__ __launch_bounds__(256) void zero_kernel() {
    const int i = blockIdx.x * 256 + threadIdx.x;
    if (i < NCELL) { g_cellcnt[i] = 0; g_cellfill[i] = 0; }
}

__global__ __launch_bounds__(256) void hist_kernel(const float* __restrict__ pts) {
    const int j = blockIdx.x * 256 + threadIdx.x;
    if (j < M_P) {
        const int c = cell_of(pts[j * 3 + 0], pts[j * 3 + 1], pts[j * 3 + 2]);
        atomicAdd(&g_cellcnt[c], 1);
    }
}

__global__ __launch_bounds__(1024) void scan_kernel() {
    __shared__ int part[1024];
    const int tid  = threadIdx.x;
    const int base = tid * 8;
    int pre[8];
    int sum = 0;
    #pragma unroll
    for (int i = 0; i < 8; i++) {
        const int idx = base + i;
        const int v = (idx < NCELL) ? g_cellcnt[idx] : 0;
        pre[i] = sum;
        sum += v;
    }
    part[tid] = sum;
    __syncthreads();
    for (int off = 1; off < 1024; off <<= 1) {
        int v = (tid >= off) ? part[tid - off] : 0;
        __syncthreads();
        part[tid] += v;
        __syncthreads();
    }
    const int offset = part[tid] - sum;
    #pragma unroll
    for (int i = 0; i < 8; i++) {
        const int idx = base + i;
        if (idx < NCELL) g_cellstart[idx] = offset + pre[i];
    }
    if (tid == 1023) g_cellstart[NCELL] = part[1023];
}

__global__ __launch_bounds__(256) void scatter_kernel(const float* __restrict__ pts) {
    const int j = blockIdx.x * 256 + threadIdx.x;
    if (j < M_P) {
        const float px = pts[j * 3 + 0];
        const float py = pts[j * 3 + 1];
        const float pz = pts[j * 3 + 2];
        const float pp = __fmaf_rn(px, px, __fmaf_rn(py, py, __fmul_rn(pz, pz)));
        const int c = cell_of(px, py, pz);
        const int slot = g_cellstart[c] + atomicAdd(&g_cellfill[c], 1);
        g_binpts[slot] = make_float4(px, py, pz, pp);
        g_binidx[slot] = j;
    }
}

// ---------------------------------------------------------------------------
// Kernel 1: top-4 NN via grid — one thread per query. Arithmetic FROZEN.
// ---------------------------------------------------------------------------
__global__ __launch_bounds__(256) void topk_grid_kernel(const float* __restrict__ q_pos) {
    const int n = blockIdx.x * 256 + threadIdx.x;
    if (n >= N_Q) return;

    const float qx = q_pos[n * 3 + 0];
    const float qy = q_pos[n * 3 + 1];
    const float qz = q_pos[n * 3 + 2];
    const float qq = __fmaf_rn(qx, qx, __fmaf_rn(qy, qy, __fmul_rn(qz, qz)));

    int cx = (int)(qx * 2.0f); cx = cx < 0 ? 0 : (cx > GRID_D - 1 ? GRID_D - 1 : cx);
    int cy = (int)(qy * 2.0f); cy = cy < 0 ? 0 : (cy > GRID_D - 1 ? GRID_D - 1 : cy);
    int cz = (int)(qz * 2.0f); cz = cz < 0 ? 0 : (cz > GRID_D - 1 ? GRID_D - 1 : cz);

    const int xlo = cx > 0 ? cx - 1 : 0, xhi = cx < GRID_D - 1 ? cx + 1 : GRID_D - 1;
    const int ylo = cy > 0 ? cy - 1 : 0, yhi = cy < GRID_D - 1 ? cy + 1 : GRID_D - 1;
    const int zlo = cz > 0 ? cz - 1 : 0, zhi = cz < GRID_D - 1 ? cz + 1 : GRID_D - 1;

    float bd[4] = {R2, R2, R2, R2};
    int   bi[4] = {IDX_SENT, IDX_SENT, IDX_SENT, IDX_SENT};

    for (int z = zlo; z <= zhi; z++) {
        for (int y = ylo; y <= yhi; y++) {
            const int crow = GRID_D * (y + GRID_D * z);
            const int s0 = g_cellstart[crow + xlo];
            const int s1 = g_cellstart[crow + xhi + 1];
            for (int s = s0; s < s1; s++) {
                const float4 p = g_binpts[s];
                const int    j = g_binidx[s];
                float dot = __fmul_rn(qx, p.x);
                dot = __fmaf_rn(qy, p.y, dot);
                dot = __fmaf_rn(qz, p.z, dot);
                const float t1 = __fadd_rn(qq, p.w);
                const float d2 = __fadd_rn(t1, -__fmul_rn(2.0f, dot));
                if (d2 <= bd[3]) {
                    if (pair_less(d2, j, bd[3], bi[3])) {
                        bd[3] = d2; bi[3] = j;
                        #pragma unroll
                        for (int q = 3; q > 0; --q) {
                            if (pair_less(bd[q], bi[q], bd[q - 1], bi[q - 1])) {
                                float td = bd[q]; bd[q] = bd[q - 1]; bd[q - 1] = td;
                                int   ti = bi[q]; bi[q] = bi[q - 1]; bi[q - 1] = ti;
                            }
                        }
                    }
                }
            }
        }
    }

    #pragma unroll
    for (int k = 0; k < 4; k++)
        g_idx[n * 4 + k] = (bi[k] == IDX_SENT) ? -1 : bi[k];
}

// ---------------------------------------------------------------------------
// Kernel 2a: convert Wagg[3072][768] -> g_B (fp16)
// ---------------------------------------------------------------------------
__global__ __launch_bounds__(256) void wconv_kernel(const float* __restrict__ Wagg) {
    const size_t id = (size_t)blockIdx.x * 256 + threadIdx.x;   // float4 index
    const float4 v = reinterpret_cast<const float4*>(Wagg)[id];
    __half2* ph = reinterpret_cast<__half2*>(g_B) + id * 2;
    ph[0] = __halves2half2(__float2half_rn(v.x), __float2half_rn(v.y));
    ph[1] = __halves2half2(__float2half_rn(v.z), __float2half_rn(v.w));
}

// ---------------------------------------------------------------------------
// Kernel 2b: gather + convert feats -> g_A [4096][3072] fp16 (192 thr, all active)
// ---------------------------------------------------------------------------
__global__ __launch_bounds__(192) void gather_kernel(const float* __restrict__ feats) {
    const int n = blockIdx.x;
    __shared__ int sl[4];
    if (threadIdx.x < 4) sl[threadIdx.x] = g_idx[n * 4 + threadIdx.x];
    __syncthreads();

    const int t = threadIdx.x;
    #pragma unroll
    for (int k = 0; k < 4; k++) {
        const int prow = sl[k];
        float4 v = make_float4(0.f, 0.f, 0.f, 0.f);
        if (prow >= 0)
            v = *reinterpret_cast<const float4*>(&feats[(size_t)prow * W_F + t * 4]);
        const size_t off = (size_t)n * K_TOT + k * W_F + t * 4;
        __half2* ph = reinterpret_cast<__half2*>(&g_A[off]);
        ph[0] = __halves2half2(__float2half_rn(v.x), __float2half_rn(v.y));
        ph[1] = __halves2half2(__float2half_rn(v.z), __float2half_rn(v.w));
    }
}

// ---------------------------------------------------------------------------
// Kernel 3: fp16 mma.sync GEMM — C = A·W, fp32 accum.
// CTA 128x64, K-tile 32, 8 warps, 3-stage cp.async, 3 CTAs/SM.
// SINGLE __syncthreads per iteration (canonical multistage): the sync at
// iter start guarantees all warps finished reading stage it-1 = slot
// (it+2)%3 before its cp.async overwrite is issued.
// ---------------------------------------------------------------------------
#define CTA_M 128
#define CTA_N 64
#define CTA_K 32
#define STAGES 3
#define NKIT (K_TOT / CTA_K)                // 96
#define LDA_B 80
#define LDB_B 144
#define A_PLANE_B (CTA_M * LDA_B)           // 10240
#define B_PLANE_B (CTA_K * LDB_B)           // 4608
#define STAGE_B (A_PLANE_B + B_PLANE_B)     // 14848
#define GEMM_SMEM (STAGES * STAGE_B)        // 44544

#define CP_ASYNC16(saddr, gaddr) \
    asm volatile("cp.async.cg.shared.global [%0], [%1], 16;" :: "r"(saddr), "l"(gaddr))
#define CP_COMMIT()  asm volatile("cp.async.commit_group;" ::: "memory")
#define CP_WAIT(n)   asm volatile("cp.async.wait_group %0;" :: "n"(n) : "memory")

__device__ __forceinline__ void ldsm_x4(uint32_t& r0, uint32_t& r1, uint32_t& r2,
                                        uint32_t& r3, uint32_t addr) {
    asm volatile("ldmatrix.sync.aligned.m8n8.x4.shared.b16 {%0,%1,%2,%3}, [%4];"
                 : "=r"(r0), "=r"(r1), "=r"(r2), "=r"(r3) : "r"(addr));
}
__device__ __forceinline__ void ldsm_x4_t(uint32_t& r0, uint32_t& r1, uint32_t& r2,
                                          uint32_t& r3, uint32_t addr) {
    asm volatile("ldmatrix.sync.aligned.m8n8.x4.trans.shared.b16 {%0,%1,%2,%3}, [%4];"
                 : "=r"(r0), "=r"(r1), "=r"(r2), "=r"(r3) : "r"(addr));
}
__device__ __forceinline__ void mma16816_f16(float* c, const uint32_t* a, const uint32_t* b) {
    asm volatile(
        "mma.sync.aligned.m16n8k16.row.col.f32.f16.f16.f32 "
        "{%0,%1,%2,%3}, {%4,%5,%6,%7}, {%8,%9}, {%0,%1,%2,%3};"
        : "+f"(c[0]), "+f"(c[1]), "+f"(c[2]), "+f"(c[3])
        : "r"(a[0]), "r"(a[1]), "r"(a[2]), "r"(a[3]), "r"(b[0]), "r"(b[1]));
}

__device__ __forceinline__ void load_stage(char* smem, int slot, int kt,
                                           int bm, int bn, int tid) {
    const uint32_t sbase = smem_u32(smem) + (uint32_t)slot * STAGE_B;
    const char* gA = reinterpret_cast<const char*>(g_A);
    const char* gB = reinterpret_cast<const char*>(g_B);

    #pragma unroll
    for (int i = 0; i < 2; i++) {
        const int id  = tid + i * 256;
        const int row = id >> 2;
        const int col = (id & 3) * 16;
        const size_t goff = ((size_t)(bm + row) * K_TOT + kt) * 2 + col;
        CP_ASYNC16(sbase + row * LDA_B + col, gA + goff);
    }
    {
        const int row = tid >> 3;
        const int col = (tid & 7) * 16;
        const size_t goff = ((size_t)(kt + row) * W_F + bn) * 2 + col;
        CP_ASYNC16(sbase + A_PLANE_B + row * LDB_B + col, gB + goff);
    }
}

__global__ __launch_bounds__(256, 3) void gemm_mma_kernel(const float* __restrict__ bagg) {
    extern __shared__ char smem[];
    const int tid  = threadIdx.x;
    const int wid  = tid >> 5;
    const int lane = tid & 31;
    const int bm = blockIdx.y * CTA_M;
    const int bn = blockIdx.x * CTA_N;
    const int wm = (wid & 3) * 32;
    const int wn = (wid >> 2) * 32;

    float c[2][4][4];
    #pragma unroll
    for (int mi = 0; mi < 2; mi++)
        #pragma unroll
        for (int ni = 0; ni < 4; ni++)
            #pragma unroll
            for (int r = 0; r < 4; r++) c[mi][ni][r] = 0.0f;

    load_stage(smem, 0, 0, bm, bn, tid); CP_COMMIT();
    load_stage(smem, 1, CTA_K, bm, bn, tid); CP_COMMIT();

    const uint32_t sb = smem_u32(smem);
    const int a_row = wm + (lane & 15);
    const int a_col = (lane >> 4) * 16;
    const int b_row = (lane & 7) + ((lane >> 3) & 1) * 8;
    const int b_col = wn + (lane >> 4) * 8;

    #pragma unroll 3
    for (int it = 0; it < NKIT; it++) {
        CP_WAIT(1);                 // stage 'it' resident
        __syncthreads();            // all warps done reading stage it-1

        // overwrite slot (it+2)%3 == (it-1)%3 — safe after the sync above
        if (it + 2 < NKIT)
            load_stage(smem, (it + 2) % STAGES, (it + 2) * CTA_K, bm, bn, tid);
        CP_COMMIT();                // unconditional: keeps wait_group(1) pattern

        const uint32_t st = sb + (uint32_t)(it % STAGES) * STAGE_B;
        const uint32_t sA = st;
        const uint32_t sB = st + A_PLANE_B;

        #pragma unroll
        for (int k16 = 0; k16 < 2; k16++) {
            uint32_t a[2][4];
            #pragma unroll
            for (int mi = 0; mi < 2; mi++) {
                const uint32_t off = (uint32_t)((a_row + mi * 16) * LDA_B
                                                + k16 * 32 + a_col);
                ldsm_x4(a[mi][0], a[mi][1], a[mi][2], a[mi][3], sA + off);
            }
            uint32_t b[4][2];
            #pragma unroll
            for (int nh = 0; nh < 2; nh++) {
                const uint32_t off = (uint32_t)((k16 * 16 + b_row) * LDB_B
                                                + (b_col + nh * 16) * 2);
                uint32_t r0, r1, r2, r3;
                ldsm_x4_t(r0, r1, r2, r3, sB + off);
                b[nh * 2 + 0][0] = r0; b[nh * 2 + 0][1] = r1;
                b[nh * 2 + 1][0] = r2; b[nh * 2 + 1][1] = r3;
            }
            #pragma unroll
            for (int mi = 0; mi < 2; mi++)
                #pragma unroll
                for (int ni = 0; ni < 4; ni++)
                    mma16816_f16(c[mi][ni], a[mi], b[ni]);
        }
    }

    #pragma unroll
    for (int mi = 0; mi < 2; mi++) {
        #pragma unroll
        for (int ni = 0; ni < 4; ni++) {
            const int row0 = bm + wm + mi * 16 + (lane >> 2);
            const int col  = bn + wn + ni * 8 + (lane & 3) * 2;
            const float bx = bagg[col], by = bagg[col + 1];
            float2 o0 = make_float2(c[mi][ni][0] + bx, c[mi][ni][1] + by);
            float2 o1 = make_float2(c[mi][ni][2] + bx, c[mi][ni][3] + by);
            *reinterpret_cast<float2*>(&g_aggraw[(size_t)row0 * W_F + col]) = o0;
            *reinterpret_cast<float2*>(&g_aggraw[(size_t)(row0 + 8) * W_F + col]) = o1;
        }
    }
}

// ---------------------------------------------------------------------------
// Kernel 4: warp-per-row pos GEMV + two LayerNorms + add. 8 rows per block.
// ---------------------------------------------------------------------------
__global__ __launch_bounds__(256) void ln_kernel(const float* __restrict__ pos_in,
                                                 const float* __restrict__ Wpos,
                                                 const float* __restrict__ bpos,
                                                 const float* __restrict__ gagg,
                                                 const float* __restrict__ beagg,
                                                 const float* __restrict__ gpos,
                                                 const float* __restrict__ bepos,
                                                 float* __restrict__ out) {
    const int wid  = threadIdx.x >> 5;
    const int lane = threadIdx.x & 31;
    const int n    = blockIdx.x * 8 + wid;

    float pin[6];
    #pragma unroll
    for (int i = 0; i < 6; i++) pin[i] = pos_in[n * 6 + i];

    float a[24], p[24];
    float sa = 0.f, sp = 0.f;
    #pragma unroll
    for (int t = 0; t < 24; t++) {
        const int j = lane + t * 32;
        a[t] = g_aggraw[(size_t)n * W_F + j];
        float pv = bpos[j];
        #pragma unroll
        for (int i = 0; i < 6; i++) pv += pin[i] * Wpos[i * W_F + j];
        p[t] = pv;
        sa += a[t]; sp += p[t];
    }
    #pragma unroll
    for (int o = 16; o > 0; o >>= 1) {
        sa += __shfl_xor_sync(0xffffffffu, sa, o);
        sp += __shfl_xor_sync(0xffffffffu, sp, o);
    }
    const float ma = sa * (1.0f / 768.0f);
    const float mp = sp * (1.0f / 768.0f);

    float va = 0.f, vp = 0.f;
    #pragma unroll
    for (int t = 0; t < 24; t++) {
        const float da = a[t] - ma; va += da * da;
        const float dp = p[t] - mp; vp += dp * dp;
    }
    #pragma unroll
    for (int o = 16; o > 0; o >>= 1) {
        va += __shfl_xor_sync(0xffffffffu, va, o);
        vp += __shfl_xor_sync(0xffffffffu, vp, o);
    }
    const float inva = rsqrtf(va * (1.0f / 768.0f) + 1e-12f);
    const float invp = rsqrtf(vp * (1.0f / 768.0f) + 1e-12f);

    #pragma unroll
    for (int t = 0; t < 24; t++) {
        const int j = lane + t * 32;
        out[(size_t)n * W_F + j] = (a[t] - ma) * inva * gagg[j] + beagg[j]
                                 + (p[t] - mp) * invp * gpos[j] + bepos[j];
    }
}

// ---------------------------------------------------------------------------
extern "C" void kernel_launch(void* const* d_in, const int* in_sizes, int n_in,
                              void* d_out, int out_size) {
    const float* q_pos  = (const float*)d_in[0];
    const float* pts    = (const float*)d_in[1];
    const float* feats  = (const float*)d_in[2];
    const float* pos_in = (const float*)d_in[3];
    const float* Wagg   = (const float*)d_in[4];
    const float* bagg   = (const float*)d_in[5];
    const float* gagg   = (const float*)d_in[6];
    const float* beagg  = (const float*)d_in[7];
    const float* Wpos   = (const float*)d_in[8];
    const float* bpos   = (const float*)d_in[9];
    const float* gpos   = (const float*)d_in[10];
    const float* bepos  = (const float*)d_in[11];
    float* out = (float*)d_out;

    static int smem_set = 0;
    if (!smem_set) {
        cudaFuncSetAttribute(gemm_mma_kernel,
                             cudaFuncAttributeMaxDynamicSharedMemorySize, GEMM_SMEM);
        smem_set = 1;
    }

    // spatial-grid kNN path
    zero_kernel<<<(NCELL + 255) / 256, 256>>>();
    hist_kernel<<<(M_P + 255) / 256, 256>>>(pts);
    scan_kernel<<<1, 1024>>>();
    scatter_kernel<<<(M_P + 255) / 256, 256>>>(pts);
    topk_grid_kernel<<<(N_Q + 255) / 256, 256>>>(q_pos);

    wconv_kernel<<<(K_TOT * W_F / 4) / 256, 256>>>(Wagg);
    gather_kernel<<<N_Q, 192>>>(feats);

    dim3 ggrid(W_F / CTA_N, N_Q / CTA_M);            // 12 x 32 = 384 CTAs
    gemm_mma_kernel<<<ggrid, 256, GEMM_SMEM>>>(bagg);

    ln_kernel<<<N_Q / 8, 256>>>(pos_in, Wpos, bpos, gagg, beagg, gpos, bepos, out);
}